// round 4
// baseline (speedup 1.0000x reference)
#include <cuda_runtime.h>
#include <math.h>
#include <stdint.h>

#define SZ 4096
#define NW (SZ*SZ)

// ---------------- scratch (static __device__, no runtime alloc) -------------
// Fragment-major layouts:
//  g_a  : A blocks m16xk8.  block(bm,bk) at ((bm*512+bk)*32+lid) float4:
//         {A[lr][lc], A[lr+8][lc], A[lr][lc+4], A[lr+8][lc+4]} (lr=lid>>2,lc=lid&3)
//  g_w*t: W^T blocks n8xk8. block(bn,bk) at ((bn*512+bk)*32+lid) float2:
//         {Wt[lr][lc], Wt[lr][lc+4]}
__device__ __align__(16) float g_a[NW];
__device__ __align__(16) float g_w1t[NW];
__device__ __align__(16) float g_w2t[NW];
__device__ double g_sums[3];   // [0]=sum log(sp) [1]=sum sp [2]=sum |w_mu|

__device__ __forceinline__ float softplusf(float x) {
    return x > 20.0f ? x : log1pf(expf(x));
}
__device__ __forceinline__ float tf32_rn(float x) {
    float y; asm("cvt.rna.tf32.f32 %0, %1;" : "=f"(y) : "f"(x)); return y;
}
__device__ __forceinline__ void cp16(uint32_t dst, const float* src) {
    asm volatile("cp.async.cg.shared.global [%0], [%1], 16;"
                 :: "r"(dst), "l"(__cvta_generic_to_global(src)));
}
__device__ __forceinline__ uint32_t smem_u32(const void* p) {
    uint32_t a;
    asm("{ .reg .u64 t; cvta.to.shared.u64 t, %1; cvt.u32.u64 %0, t; }"
        : "=r"(a) : "l"(p));
    return a;
}

#define MMA_TF32(d, a0, a1, a2, a3, b0, b1) \
    asm volatile( \
        "mma.sync.aligned.m16n8k8.row.col.f32.tf32.tf32.f32 " \
        "{%0,%1,%2,%3}, {%4,%5,%6,%7}, {%8,%9}, {%0,%1,%2,%3};" \
        : "+f"((d)[0]), "+f"((d)[1]), "+f"((d)[2]), "+f"((d)[3]) \
        : "r"(__float_as_uint(a0)), "r"(__float_as_uint(a1)), \
          "r"(__float_as_uint(a2)), "r"(__float_as_uint(a3)), \
          "r"(__float_as_uint(b0)), "r"(__float_as_uint(b1)))

// ---------------- prep kernels ----------------------------------------------
__global__ void init_kernel() {
    if (threadIdx.x < 3) g_sums[threadIdx.x] = 0.0;
}

// A: tf32-round + permute to fragment-major
__global__ __launch_bounds__(256) void prep_a(const float* __restrict__ mu) {
    __shared__ float t[64][68];
    const int bx = blockIdx.x * 64;   // k
    const int by = blockIdx.y * 64;   // m
    const int tid = threadIdx.x;
    const int wid = tid >> 5, lid = tid & 31;
#pragma unroll
    for (int i = 0; i < 4; i++) {
        int slot = tid + i * 256;
        int row = slot >> 4, c4 = slot & 15;
        float4 v = *(const float4*)(mu + (size_t)(by + row) * SZ + bx + c4 * 4);
        t[row][c4 * 4 + 0] = tf32_rn(v.x);
        t[row][c4 * 4 + 1] = tf32_rn(v.y);
        t[row][c4 * 4 + 2] = tf32_rn(v.z);
        t[row][c4 * 4 + 3] = tf32_rn(v.w);
    }
    __syncthreads();
    const int lr = lid >> 2, lc = lid & 3;
    float4* ga4 = (float4*)g_a;
#pragma unroll
    for (int j = 0; j < 4; j++) {
        int b = wid * 4 + j;          // 32 blocks: bm[4] x bk[8]
        int bm = b >> 3, bk = b & 7;
        float4 o;
        o.x = t[bm * 16 + lr][bk * 8 + lc];
        o.y = t[bm * 16 + lr + 8][bk * 8 + lc];
        o.z = t[bm * 16 + lr][bk * 8 + lc + 4];
        o.w = t[bm * 16 + lr + 8][bk * 8 + lc + 4];
        size_t gi = ((size_t)(by / 16 + bm) * 512 + (bx / 8 + bk)) * 32 + lid;
        ga4[gi] = o;
    }
}

// W: softplus + tf32-round + transpose + permute to fragment-major + KL sums
__global__ void prep_w(const float* __restrict__ w_mu,
                       const float* __restrict__ w_sigma) {
    __shared__ float t1[32][33];
    __shared__ float t2[32][33];
    __shared__ float red[3][256];
    const int bx = blockIdx.x * 32;   // n
    const int by = blockIdx.y * 32;   // k
    const int tx = threadIdx.x, ty = threadIdx.y;
    const int tid = ty * 32 + tx;

    float s_log = 0.f, s_sp = 0.f, s_abs = 0.f;
#pragma unroll
    for (int i = 0; i < 4; i++) {
        int k = by + ty + i * 8;
        int n = bx + tx;
        float wm = w_mu[(size_t)k * SZ + n];
        float ws = w_sigma[(size_t)k * SZ + n];
        float sp = softplusf(ws);
        s_log += logf(sp);
        s_sp  += sp;
        s_abs += fabsf(wm);
        t1[ty + i * 8][tx] = tf32_rn(wm);   // t[k_local][n_local]
        t2[ty + i * 8][tx] = tf32_rn(sp);
    }
    __syncthreads();

    const int wid = tid >> 5, lid = tid & 31;
    const int lr = lid >> 2, lc = lid & 3;
    float2* gw1 = (float2*)g_w1t;
    float2* gw2 = (float2*)g_w2t;
#pragma unroll
    for (int j = 0; j < 2; j++) {
        int b = wid * 2 + j;          // 16 blocks: bn[4] x bk[4]
        int bn = b >> 2, bk = b & 3;
        float2 o1, o2;
        o1.x = t1[bk * 8 + lc][bn * 8 + lr];
        o1.y = t1[bk * 8 + lc + 4][bn * 8 + lr];
        o2.x = t2[bk * 8 + lc][bn * 8 + lr];
        o2.y = t2[bk * 8 + lc + 4][bn * 8 + lr];
        size_t gi = ((size_t)(bx / 8 + bn) * 512 + (by / 8 + bk)) * 32 + lid;
        gw1[gi] = o1;
        gw2[gi] = o2;
    }

    red[0][tid] = s_log; red[1][tid] = s_sp; red[2][tid] = s_abs;
    __syncthreads();
    for (int off = 128; off > 0; off >>= 1) {
        if (tid < off) {
            red[0][tid] += red[0][tid + off];
            red[1][tid] += red[1][tid + off];
            red[2][tid] += red[2][tid + off];
        }
        __syncthreads();
    }
    if (tid == 0) {
        atomicAdd(&g_sums[0], (double)red[0][0]);
        atomicAdd(&g_sums[1], (double)red[1][0]);
        atomicAdd(&g_sums[2], (double)red[2][0]);
    }
}

__global__ void finalize_kl(float* __restrict__ out) {
    double mean_log = g_sums[0] / (double)NW;
    double mean_sp  = g_sums[1] / (double)NW;
    double kl = -0.5 * ((double)SZ * mean_log - g_sums[2] - (double)SZ * mean_sp);
    out[(size_t)2 * SZ * SZ] = (float)kl;
}

// ---------------- main dual GEMM (fragment-major, mma.sync tf32) -------------
// CTA: 128x128 both paths; 8 warps (2m x 4n), warp tile 64x32.
#define NCHUNK 128            // K chunks of 32
#define STAGES 4
#define STAGE_BYTES 49152     // A 16KB + W1 16KB + W2 16KB
#define SMEM_TOTAL (STAGES * STAGE_BYTES)   // 196608

__global__ __launch_bounds__(256, 1)
void gemm_tf32(const float* __restrict__ b_mu,
               const float* __restrict__ b_sigma,
               float* __restrict__ out) {
    extern __shared__ char smem[];
    const uint32_t sb = smem_u32(smem);
    const int tid = threadIdx.x;
    const int wid = tid >> 5;
    const int lid = tid & 31;
    const int lr  = lid >> 2;
    const int lc  = lid & 3;
    const int wm  = wid & 1;
    const int wn  = wid >> 1;
    const int mblk0 = blockIdx.y * 8;     // m16-block base
    const int nblk0 = blockIdx.x * 16;    // n8-block base

    float acc1[4][4][4];
    float acc2[4][4][4];
#pragma unroll
    for (int mt = 0; mt < 4; mt++)
#pragma unroll
        for (int nt = 0; nt < 4; nt++)
#pragma unroll
            for (int q = 0; q < 4; q++) { acc1[mt][nt][q] = 0.f; acc2[mt][nt][q] = 0.f; }

    const float4* ga4 = (const float4*)g_a;
    const float4* gw14 = (const float4*)g_w1t;
    const float4* gw24 = (const float4*)g_w2t;

    auto load_stage = [&](int c, int s) {
        const int bk0 = c * 4;
        const uint32_t base = sb + s * STAGE_BYTES;
#pragma unroll
        for (int i = 0; i < 4; i++) {
            int slot = tid + i * 256;          // 0..1023 (x 16B)
            {   // A tile: 8 m-blocks x (4 kb * 32 lanes) float4
                int mb = slot >> 7, r = slot & 127;
                size_t gi = ((size_t)(mblk0 + mb) * 512 + bk0) * 32 + r;
                cp16(base + slot * 16, (const float*)(ga4 + gi));
            }
            {   // W tiles: 16 n-blocks x (4 kb * 16) float4
                int nb = slot >> 6, r = slot & 63;
                size_t gi = ((size_t)(nblk0 + nb) * 512 + bk0) * 16 + r;
                cp16(base + 16384 + slot * 16, (const float*)(gw14 + gi));
                cp16(base + 32768 + slot * 16, (const float*)(gw24 + gi));
            }
        }
        asm volatile("cp.async.commit_group;" ::: "memory");
    };

    load_stage(0, 0);
    load_stage(1, 1);
    load_stage(2, 2);

    for (int c = 0; c < NCHUNK; c++) {
        const int s = c & 3;
        asm volatile("cp.async.wait_group 2;" ::: "memory");
        __syncthreads();
        if (c + 3 < NCHUNK) load_stage(c + 3, (c + 3) & 3);
        else asm volatile("cp.async.commit_group;" ::: "memory");

        const char* st = smem + s * STAGE_BYTES;
#pragma unroll
        for (int ks = 0; ks < 4; ks++) {
            float4 af[4], a2f[4];
#pragma unroll
            for (int mt = 0; mt < 4; mt++) {
                af[mt] = *(const float4*)(st + ((((wm * 4 + mt) * 4 + ks) * 32 + lid) << 4));
                a2f[mt].x = tf32_rn(af[mt].x * af[mt].x);
                a2f[mt].y = tf32_rn(af[mt].y * af[mt].y);
                a2f[mt].z = tf32_rn(af[mt].z * af[mt].z);
                a2f[mt].w = tf32_rn(af[mt].w * af[mt].w);
            }
#pragma unroll
            for (int nt = 0; nt < 4; nt++) {
                const char* wp = st + 16384 + ((((wn * 4 + nt) * 4 + ks) * 32 + lid) << 3);
                float2 w1 = *(const float2*)wp;
                float2 w2 = *(const float2*)(wp + 16384);
#pragma unroll
                for (int mt = 0; mt < 4; mt++)
                    MMA_TF32(acc1[mt][nt], af[mt].x, af[mt].y, af[mt].z, af[mt].w,
                             w1.x, w1.y);
#pragma unroll
                for (int mt = 0; mt < 4; mt++)
                    MMA_TF32(acc2[mt][nt], a2f[mt].x, a2f[mt].y, a2f[mt].z, a2f[mt].w,
                             w2.x, w2.y);
            }
        }
    }

    // ---------------- epilogue ----------------
    const int m0 = blockIdx.y * 128;
    const int n0 = blockIdx.x * 128;
    float* o1 = out;
    float* o2 = out + (size_t)SZ * SZ;
#pragma unroll
    for (int nt = 0; nt < 4; nt++) {
        int col = n0 + wn * 32 + nt * 8 + lc * 2;
        float bm0 = b_mu[col],  bm1 = b_mu[col + 1];
        float bs0 = softplusf(b_sigma[col]), bs1 = softplusf(b_sigma[col + 1]);
#pragma unroll
        for (int mt = 0; mt < 4; mt++) {
            int row = m0 + wm * 64 + mt * 16 + lr;
            float2 v;
            v.x = acc1[mt][nt][0] + bm0; v.y = acc1[mt][nt][1] + bm1;
            *(float2*)(o1 + (size_t)row * SZ + col) = v;
            v.x = acc1[mt][nt][2] + bm0; v.y = acc1[mt][nt][3] + bm1;
            *(float2*)(o1 + (size_t)(row + 8) * SZ + col) = v;
            v.x = acc2[mt][nt][0] + bs0; v.y = acc2[mt][nt][1] + bs1;
            *(float2*)(o2 + (size_t)row * SZ + col) = v;
            v.x = acc2[mt][nt][2] + bs0; v.y = acc2[mt][nt][3] + bs1;
            *(float2*)(o2 + (size_t)(row + 8) * SZ + col) = v;
        }
    }
}

// ---------------- launch -----------------------------------------------------
extern "C" void kernel_launch(void* const* d_in, const int* in_sizes, int n_in,
                              void* d_out, int out_size) {
    const float* mu_in   = (const float*)d_in[0];
    // d_in[1] = sigma_in : unused by the reference outputs
    const float* w_mu    = (const float*)d_in[2];
    const float* w_sigma = (const float*)d_in[3];
    const float* b_mu    = (const float*)d_in[4];
    const float* b_sigma = (const float*)d_in[5];
    float* out = (float*)d_out;

    cudaFuncSetAttribute(gemm_tf32, cudaFuncAttributeMaxDynamicSharedMemorySize,
                         SMEM_TOTAL);

    init_kernel<<<1, 32>>>();
    prep_w<<<dim3(128, 128), dim3(32, 8)>>>(w_mu, w_sigma);
    prep_a<<<dim3(64, 64), 256>>>(mu_in);
    gemm_tf32<<<dim3(SZ / 128, SZ / 128), 256, SMEM_TOTAL>>>(b_mu, b_sigma, out);
    finalize_kl<<<1, 1>>>(out);
}

// round 5
// speedup vs baseline: 1.2241x; 1.2241x over previous
#include <cuda_runtime.h>
#include <math.h>
#include <stdint.h>

#define SZ 4096
#define NW (SZ*SZ)

// ---------------- scratch (static __device__, no runtime alloc) -------------
__device__ float  g_a[NW];     // tf32-rounded mu_in         [B][K]
__device__ float  g_w1t[NW];   // tf32-rounded w_mu^T        [N][K]
__device__ float  g_w2t[NW];   // tf32-rounded sp(w_sigma)^T [N][K]
__device__ double g_sums[3];   // [0]=sum log(sp) [1]=sum sp [2]=sum |w_mu|

__device__ __forceinline__ float softplusf(float x) {
    return x > 20.0f ? x : log1pf(expf(x));
}
__device__ __forceinline__ float tf32_rn(float x) {
    float y; asm("cvt.rna.tf32.f32 %0, %1;" : "=f"(y) : "f"(x)); return y;
}
__device__ __forceinline__ void cp16(uint32_t dst, const float* src) {
    asm volatile("cp.async.cg.shared.global [%0], [%1], 16;"
                 :: "r"(dst), "l"(__cvta_generic_to_global(src)));
}
__device__ __forceinline__ uint32_t smem_u32(const void* p) {
    uint32_t a;
    asm("{ .reg .u64 t; cvta.to.shared.u64 t, %1; cvt.u32.u64 %0, t; }"
        : "=r"(a) : "l"(p));
    return a;
}

#define MMA_TF32(d, a0, a1, a2, a3, b0, b1) \
    asm volatile( \
        "mma.sync.aligned.m16n8k8.row.col.f32.tf32.tf32.f32 " \
        "{%0,%1,%2,%3}, {%4,%5,%6,%7}, {%8,%9}, {%0,%1,%2,%3};" \
        : "+f"((d)[0]), "+f"((d)[1]), "+f"((d)[2]), "+f"((d)[3]) \
        : "r"(__float_as_uint(a0)), "r"(__float_as_uint(a1)), \
          "r"(__float_as_uint(a2)), "r"(__float_as_uint(a3)), \
          "r"(__float_as_uint(b0)), "r"(__float_as_uint(b1)))

// ---------------- prep kernels ----------------------------------------------
__global__ void init_kernel() {
    if (threadIdx.x < 3) g_sums[threadIdx.x] = 0.0;
}

// transpose + softplus + tf32 rounding + KL reduction
__global__ void prep_w(const float* __restrict__ w_mu,
                       const float* __restrict__ w_sigma) {
    __shared__ float t1[32][33];
    __shared__ float t2[32][33];
    __shared__ float red[3][256];
    const int bx = blockIdx.x * 32;   // n
    const int by = blockIdx.y * 32;   // k
    const int tx = threadIdx.x, ty = threadIdx.y;
    const int tid = ty * 32 + tx;

    float s_log = 0.f, s_sp = 0.f, s_abs = 0.f;
#pragma unroll
    for (int i = 0; i < 4; i++) {
        int k = by + ty + i * 8;
        int n = bx + tx;
        float wm = w_mu[(size_t)k * SZ + n];
        float ws = w_sigma[(size_t)k * SZ + n];
        float sp = softplusf(ws);
        s_log += logf(sp);
        s_sp  += sp;
        s_abs += fabsf(wm);
        t1[ty + i * 8][tx] = tf32_rn(wm);
        t2[ty + i * 8][tx] = tf32_rn(sp);
    }
    __syncthreads();
#pragma unroll
    for (int i = 0; i < 4; i++) {
        int n = bx + ty + i * 8;
        int k = by + tx;
        g_w1t[(size_t)n * SZ + k] = t1[tx][ty + i * 8];
        g_w2t[(size_t)n * SZ + k] = t2[tx][ty + i * 8];
    }

    red[0][tid] = s_log; red[1][tid] = s_sp; red[2][tid] = s_abs;
    __syncthreads();
    for (int off = 128; off > 0; off >>= 1) {
        if (tid < off) {
            red[0][tid] += red[0][tid + off];
            red[1][tid] += red[1][tid + off];
            red[2][tid] += red[2][tid + off];
        }
        __syncthreads();
    }
    if (tid == 0) {
        atomicAdd(&g_sums[0], (double)red[0][0]);
        atomicAdd(&g_sums[1], (double)red[1][0]);
        atomicAdd(&g_sums[2], (double)red[2][0]);
    }
}

__global__ void prep_a(const float* __restrict__ mu) {
    const float4* m4 = (const float4*)mu;
    float4* a4 = (float4*)g_a;
    int stride = gridDim.x * blockDim.x;
    for (int i = blockIdx.x * blockDim.x + threadIdx.x; i < NW / 4; i += stride) {
        float4 x = m4[i];
        float4 a;
        a.x = tf32_rn(x.x); a.y = tf32_rn(x.y);
        a.z = tf32_rn(x.z); a.w = tf32_rn(x.w);
        a4[i] = a;
    }
}

__global__ void finalize_kl(float* __restrict__ out) {
    double mean_log = g_sums[0] / (double)NW;
    double mean_sp  = g_sums[1] / (double)NW;
    double kl = -0.5 * ((double)SZ * mean_log - g_sums[2] - (double)SZ * mean_sp);
    out[(size_t)2 * SZ * SZ] = (float)kl;
}

// ---------------- main dual GEMM on mma.sync tf32 ----------------------------
// CTA: 128x128, both paths. 512 threads = 16 warps (4m x 4n), warp tile 32x32.
#define BM 128
#define BN 128
#define BK 32
#define STAGES 3
#define NCHUNK (SZ / BK)       // 128
#define PITCH 36               // floats per smem row (conflict-free)

#define TILE_BYTES (128 * PITCH * 4)       // 18432 per operand tile
#define STAGE_BYTES (3 * TILE_BYTES)       // A, W1, W2
#define SMEM_TOTAL (STAGES * STAGE_BYTES)  // 165888

__global__ __launch_bounds__(512, 1)
void gemm_tf32(const float* __restrict__ b_mu,
               const float* __restrict__ b_sigma,
               float* __restrict__ out) {
    extern __shared__ char smem[];
    const uint32_t sb = smem_u32(smem);

    const int tid = threadIdx.x;
    const int wid = tid >> 5;
    const int lid = tid & 31;
    const int lr  = lid >> 2;     // 0..7
    const int lc  = lid & 3;      // 0..3
    const int wm  = wid & 3;      // m-block (32 rows)
    const int wn  = wid >> 2;     // n-block (32 cols)
    const int m0 = blockIdx.y * BM;
    const int n0 = blockIdx.x * BN;

    float acc1[2][4][4];   // [mt][nt][4]
    float acc2[2][4][4];
#pragma unroll
    for (int mt = 0; mt < 2; mt++)
#pragma unroll
        for (int nt = 0; nt < 4; nt++)
#pragma unroll
            for (int q = 0; q < 4; q++) { acc1[mt][nt][q] = 0.f; acc2[mt][nt][q] = 0.f; }

    // Stage loader: 6 x 16B cp.async per thread (A, W1, W2: 128x32 floats each)
    auto load_stage = [&](int chunk, int s) {
        const int k0 = chunk * BK;
        const uint32_t base = sb + s * STAGE_BYTES;
#pragma unroll
        for (int i = 0; i < 2; i++) {
            int f = tid + i * 512;         // 0..1023
            int r = f >> 3, c4 = f & 7;
            uint32_t doff = (uint32_t)(r * (PITCH * 4) + c4 * 16);
            size_t goff = (size_t)(m0 + r) * SZ + k0 + c4 * 4;
            cp16(base + doff, g_a + goff);
            size_t woff = (size_t)(n0 + r) * SZ + k0 + c4 * 4;
            cp16(base + TILE_BYTES + doff,     g_w1t + woff);
            cp16(base + 2 * TILE_BYTES + doff, g_w2t + woff);
        }
        asm volatile("cp.async.commit_group;" ::: "memory");
    };

    // Prologue: prefetch STAGES-1 chunks
    load_stage(0, 0);
    load_stage(1, 1);

    for (int c = 0; c < NCHUNK; c++) {
        const int s = c % STAGES;
        asm volatile("cp.async.wait_group %0;" :: "n"(STAGES - 2) : "memory");
        __syncthreads();

        // prefetch chunk c+STAGES-1 into the stage freed at iteration c-1
        if (c + STAGES - 1 < NCHUNK)
            load_stage(c + STAGES - 1, (c + STAGES - 1) % STAGES);

        const float* As  = (const float*)(smem + s * STAGE_BYTES);
        const float* W1s = (const float*)(smem + s * STAGE_BYTES + TILE_BYTES);
        const float* W2s = (const float*)(smem + s * STAGE_BYTES + 2 * TILE_BYTES);

#pragma unroll
        for (int ks = 0; ks < BK / 8; ks++) {
            const int k0 = ks * 8;
            float a[2][4], a2[2][4];
#pragma unroll
            for (int mt = 0; mt < 2; mt++) {
                const float* p = As + (wm * 32 + mt * 16 + lr) * PITCH + k0 + lc;
                a[mt][0] = p[0];
                a[mt][1] = p[8 * PITCH];
                a[mt][2] = p[4];
                a[mt][3] = p[8 * PITCH + 4];
#pragma unroll
                for (int q = 0; q < 4; q++)
                    a2[mt][q] = tf32_rn(a[mt][q] * a[mt][q]);
            }
#pragma unroll
            for (int nt = 0; nt < 4; nt++) {
                const float* p1 = W1s + (wn * 32 + nt * 8 + lr) * PITCH + k0 + lc;
                float b0 = p1[0], b1 = p1[4];
#pragma unroll
                for (int mt = 0; mt < 2; mt++)
                    MMA_TF32(acc1[mt][nt], a[mt][0], a[mt][1], a[mt][2], a[mt][3], b0, b1);
                const float* p2 = W2s + (wn * 32 + nt * 8 + lr) * PITCH + k0 + lc;
                float c0 = p2[0], c1 = p2[4];
#pragma unroll
                for (int mt = 0; mt < 2; mt++)
                    MMA_TF32(acc2[mt][nt], a2[mt][0], a2[mt][1], a2[mt][2], a2[mt][3], c0, c1);
            }
        }
        __syncthreads();
    }

    // ---------------- epilogue ----------------
    float* o1 = out;
    float* o2 = out + (size_t)SZ * SZ;
#pragma unroll
    for (int nt = 0; nt < 4; nt++) {
        int col = n0 + wn * 32 + nt * 8 + lc * 2;
        float bm0 = b_mu[col],  bm1 = b_mu[col + 1];
        float bs0 = softplusf(b_sigma[col]), bs1 = softplusf(b_sigma[col + 1]);
#pragma unroll
        for (int mt = 0; mt < 2; mt++) {
            int row = m0 + wm * 32 + mt * 16 + lr;
            float2 v;
            v.x = acc1[mt][nt][0] + bm0; v.y = acc1[mt][nt][1] + bm1;
            *(float2*)(o1 + (size_t)row * SZ + col) = v;
            v.x = acc1[mt][nt][2] + bm0; v.y = acc1[mt][nt][3] + bm1;
            *(float2*)(o1 + (size_t)(row + 8) * SZ + col) = v;
            v.x = acc2[mt][nt][0] + bs0; v.y = acc2[mt][nt][1] + bs1;
            *(float2*)(o2 + (size_t)row * SZ + col) = v;
            v.x = acc2[mt][nt][2] + bs0; v.y = acc2[mt][nt][3] + bs1;
            *(float2*)(o2 + (size_t)(row + 8) * SZ + col) = v;
        }
    }
}

// ---------------- launch -----------------------------------------------------
extern "C" void kernel_launch(void* const* d_in, const int* in_sizes, int n_in,
                              void* d_out, int out_size) {
    const float* mu_in   = (const float*)d_in[0];
    // d_in[1] = sigma_in : unused by the reference outputs
    const float* w_mu    = (const float*)d_in[2];
    const float* w_sigma = (const float*)d_in[3];
    const float* b_mu    = (const float*)d_in[4];
    const float* b_sigma = (const float*)d_in[5];
    float* out = (float*)d_out;

    cudaFuncSetAttribute(gemm_tf32, cudaFuncAttributeMaxDynamicSharedMemorySize,
                         SMEM_TOTAL);

    init_kernel<<<1, 32>>>();
    prep_w<<<dim3(128, 128), dim3(32, 8)>>>(w_mu, w_sigma);
    prep_a<<<4096, 256>>>(mu_in);
    gemm_tf32<<<dim3(SZ / BN, SZ / BM), 512, SMEM_TOTAL>>>(b_mu, b_sigma, out);
    finalize_kl<<<1, 1>>>(out);
}

// round 6
// speedup vs baseline: 1.3628x; 1.1133x over previous
#include <cuda_runtime.h>
#include <math.h>
#include <stdint.h>

#define SZ 4096
#define NW (SZ*SZ)

// ---------------- scratch (static __device__, no runtime alloc) -------------
__device__ float  g_a[NW];     // tf32-rounded mu_in         [B][K]
__device__ float  g_w1t[NW];   // tf32-rounded w_mu^T        [N][K]
__device__ float  g_w2t[NW];   // tf32-rounded sp(w_sigma)^T [N][K]
__device__ double g_sums[3];   // [0]=sum log(sp) [1]=sum sp [2]=sum |w_mu|

__device__ __forceinline__ float softplusf(float x) {
    return x > 20.0f ? x : log1pf(expf(x));
}
__device__ __forceinline__ float tf32_rn(float x) {
    float y; asm("cvt.rna.tf32.f32 %0, %1;" : "=f"(y) : "f"(x)); return y;
}
__device__ __forceinline__ void cp16(uint32_t dst, const float* src) {
    asm volatile("cp.async.cg.shared.global [%0], [%1], 16;"
                 :: "r"(dst), "l"(__cvta_generic_to_global(src)));
}
__device__ __forceinline__ uint32_t smem_u32(const void* p) {
    uint32_t a;
    asm("{ .reg .u64 t; cvta.to.shared.u64 t, %1; cvt.u32.u64 %0, t; }"
        : "=r"(a) : "l"(p));
    return a;
}

#define LDSM4(r0, r1, r2, r3, addr) \
    asm volatile("ldmatrix.sync.aligned.m8n8.x4.shared.b16 {%0,%1,%2,%3}, [%4];" \
        : "=r"(r0), "=r"(r1), "=r"(r2), "=r"(r3) : "r"(addr))

// MMA with uint32 a-regs
#define MMA_TF32U(d, a0, a1, a2, a3, b0, b1) \
    asm volatile( \
        "mma.sync.aligned.m16n8k8.row.col.f32.tf32.tf32.f32 " \
        "{%0,%1,%2,%3}, {%4,%5,%6,%7}, {%8,%9}, {%0,%1,%2,%3};" \
        : "+f"((d)[0]), "+f"((d)[1]), "+f"((d)[2]), "+f"((d)[3]) \
        : "r"(a0), "r"(a1), "r"(a2), "r"(a3), "r"(b0), "r"(b1))

// ---------------- prep kernels ----------------------------------------------
__global__ void init_kernel() {
    if (threadIdx.x < 3) g_sums[threadIdx.x] = 0.0;
}

// transpose + softplus + tf32 rounding + KL reduction
__global__ void prep_w(const float* __restrict__ w_mu,
                       const float* __restrict__ w_sigma) {
    __shared__ float t1[32][33];
    __shared__ float t2[32][33];
    __shared__ float red[3][256];
    const int bx = blockIdx.x * 32;   // n
    const int by = blockIdx.y * 32;   // k
    const int tx = threadIdx.x, ty = threadIdx.y;
    const int tid = ty * 32 + tx;

    float s_log = 0.f, s_sp = 0.f, s_abs = 0.f;
#pragma unroll
    for (int i = 0; i < 4; i++) {
        int k = by + ty + i * 8;
        int n = bx + tx;
        float wm = w_mu[(size_t)k * SZ + n];
        float ws = w_sigma[(size_t)k * SZ + n];
        float sp = softplusf(ws);
        s_log += logf(sp);
        s_sp  += sp;
        s_abs += fabsf(wm);
        t1[ty + i * 8][tx] = tf32_rn(wm);
        t2[ty + i * 8][tx] = tf32_rn(sp);
    }
    __syncthreads();
#pragma unroll
    for (int i = 0; i < 4; i++) {
        int n = bx + ty + i * 8;
        int k = by + tx;
        g_w1t[(size_t)n * SZ + k] = t1[tx][ty + i * 8];
        g_w2t[(size_t)n * SZ + k] = t2[tx][ty + i * 8];
    }

    red[0][tid] = s_log; red[1][tid] = s_sp; red[2][tid] = s_abs;
    __syncthreads();
    for (int off = 128; off > 0; off >>= 1) {
        if (tid < off) {
            red[0][tid] += red[0][tid + off];
            red[1][tid] += red[1][tid + off];
            red[2][tid] += red[2][tid + off];
        }
        __syncthreads();
    }
    if (tid == 0) {
        atomicAdd(&g_sums[0], (double)red[0][0]);
        atomicAdd(&g_sums[1], (double)red[1][0]);
        atomicAdd(&g_sums[2], (double)red[2][0]);
    }
}

__global__ void prep_a(const float* __restrict__ mu) {
    const float4* m4 = (const float4*)mu;
    float4* a4 = (float4*)g_a;
    int stride = gridDim.x * blockDim.x;
    for (int i = blockIdx.x * blockDim.x + threadIdx.x; i < NW / 4; i += stride) {
        float4 x = m4[i];
        float4 a;
        a.x = tf32_rn(x.x); a.y = tf32_rn(x.y);
        a.z = tf32_rn(x.z); a.w = tf32_rn(x.w);
        a4[i] = a;
    }
}

__global__ void finalize_kl(float* __restrict__ out) {
    double mean_log = g_sums[0] / (double)NW;
    double mean_sp  = g_sums[1] / (double)NW;
    double kl = -0.5 * ((double)SZ * mean_log - g_sums[2] - (double)SZ * mean_sp);
    out[(size_t)2 * SZ * SZ] = (float)kl;
}

// ---------------- main dual GEMM (mma.sync tf32 + ldmatrix) ------------------
// CTA: 128x128, both paths. 256 threads, 8 warps (2m x 4n), warp tile 64x32.
#define BM 128
#define BN 128
#define BK 32
#define STAGES 4
#define NCHUNK (SZ / BK)       // 128
#define PITCH 36               // floats per smem row (conflict-free for LDS+LDSM)

#define TILE_BYTES (128 * PITCH * 4)        // 18432 per operand tile
#define STAGE_BYTES (3 * TILE_BYTES)        // A, W1, W2
#define SMEM_TOTAL (STAGES * STAGE_BYTES)   // 221184

__global__ __launch_bounds__(256, 1)
void gemm_tf32(const float* __restrict__ b_mu,
               const float* __restrict__ b_sigma,
               float* __restrict__ out) {
    extern __shared__ char smem[];
    const uint32_t sb = smem_u32(smem);

    const int tid = threadIdx.x;
    const int wid = tid >> 5;
    const int lid = tid & 31;
    const int lr  = lid >> 2;     // 0..7
    const int lc  = lid & 3;      // 0..3
    const int wm  = wid & 1;      // m-block (64 rows)
    const int wn  = wid >> 1;     // n-block (32 cols)
    const int m0 = blockIdx.y * BM;
    const int n0 = blockIdx.x * BN;

    // ldmatrix per-lane source offsets (bytes)
    const int lrow = lid & 7;
    const int lmat = lid >> 3;
    // A x4: mats {rows0-7 klo, rows8-15 klo, rows0-7 khi, rows8-15 khi}
    const uint32_t offA = (uint32_t)((((lmat & 1) * 8 + lrow) * PITCH + (lmat >> 1) * 4) * 4);
    // W x4: mats {nblk0 klo, nblk0 khi, nblk1 klo, nblk1 khi}
    const uint32_t offW = (uint32_t)((((lmat >> 1) * 8 + lrow) * PITCH + (lmat & 1) * 4) * 4);

    uint32_t relA[4], relW[2];
#pragma unroll
    for (int mt = 0; mt < 4; mt++)
        relA[mt] = (uint32_t)((wm * 64 + mt * 16) * PITCH * 4) + offA;
#pragma unroll
    for (int ntp = 0; ntp < 2; ntp++)
        relW[ntp] = (uint32_t)((wn * 32 + ntp * 16) * PITCH * 4) + offW;

    float acc1[4][4][4];
    float acc2[4][4][4];
#pragma unroll
    for (int mt = 0; mt < 4; mt++)
#pragma unroll
        for (int nt = 0; nt < 4; nt++)
#pragma unroll
            for (int q = 0; q < 4; q++) { acc1[mt][nt][q] = 0.f; acc2[mt][nt][q] = 0.f; }

    // Stage loader: 12 x 16B cp.async per thread
    auto load_stage = [&](int chunk, int s) {
        const int k0 = chunk * BK;
        const uint32_t base = sb + s * STAGE_BYTES;
#pragma unroll
        for (int i = 0; i < 4; i++) {
            int f = tid + i * 256;         // 0..1023
            int r = f >> 3, c4 = f & 7;
            uint32_t doff = (uint32_t)(r * (PITCH * 4) + c4 * 16);
            size_t goff = (size_t)(m0 + r) * SZ + k0 + c4 * 4;
            cp16(base + doff, g_a + goff);
            size_t woff = (size_t)(n0 + r) * SZ + k0 + c4 * 4;
            cp16(base + TILE_BYTES + doff,     g_w1t + woff);
            cp16(base + 2 * TILE_BYTES + doff, g_w2t + woff);
        }
        asm volatile("cp.async.commit_group;" ::: "memory");
    };

    load_stage(0, 0);
    load_stage(1, 1);
    load_stage(2, 2);

    for (int c = 0; c < NCHUNK; c++) {
        const int s = c & 3;
        asm volatile("cp.async.wait_group 2;" ::: "memory");
        __syncthreads();
        if (c + 3 < NCHUNK) load_stage(c + 3, (c + 3) & 3);
        else asm volatile("cp.async.commit_group;" ::: "memory");

        const uint32_t stA  = sb + s * STAGE_BYTES;
        const uint32_t stW1 = stA + TILE_BYTES;
        const uint32_t stW2 = stA + 2 * TILE_BYTES;

#pragma unroll
        for (int ks = 0; ks < BK / 8; ks++) {
            const uint32_t kb = (uint32_t)(ks * 32);   // ks*8 floats
            uint32_t af[4][4];
            uint32_t a2f[4][4];
#pragma unroll
            for (int mt = 0; mt < 4; mt++) {
                LDSM4(af[mt][0], af[mt][1], af[mt][2], af[mt][3], stA + relA[mt] + kb);
#pragma unroll
                for (int q = 0; q < 4; q++) {
                    float v = __uint_as_float(af[mt][q]);
                    a2f[mt][q] = __float_as_uint(tf32_rn(v * v));
                }
            }
            uint32_t w1f[2][4], w2f[2][4];
#pragma unroll
            for (int ntp = 0; ntp < 2; ntp++) {
                LDSM4(w1f[ntp][0], w1f[ntp][1], w1f[ntp][2], w1f[ntp][3],
                      stW1 + relW[ntp] + kb);
                LDSM4(w2f[ntp][0], w2f[ntp][1], w2f[ntp][2], w2f[ntp][3],
                      stW2 + relW[ntp] + kb);
            }
#pragma unroll
            for (int ntp = 0; ntp < 2; ntp++) {
#pragma unroll
                for (int h = 0; h < 2; h++) {
                    const int nt = ntp * 2 + h;
                    const uint32_t b0 = w1f[ntp][h * 2], b1 = w1f[ntp][h * 2 + 1];
#pragma unroll
                    for (int mt = 0; mt < 4; mt++)
                        MMA_TF32U(acc1[mt][nt], af[mt][0], af[mt][1], af[mt][2],
                                  af[mt][3], b0, b1);
                    const uint32_t c0 = w2f[ntp][h * 2], c1 = w2f[ntp][h * 2 + 1];
#pragma unroll
                    for (int mt = 0; mt < 4; mt++)
                        MMA_TF32U(acc2[mt][nt], a2f[mt][0], a2f[mt][1], a2f[mt][2],
                                  a2f[mt][3], c0, c1);
                }
            }
        }
    }

    // ---------------- epilogue ----------------
    float* o1 = out;
    float* o2 = out + (size_t)SZ * SZ;
#pragma unroll
    for (int nt = 0; nt < 4; nt++) {
        int col = n0 + wn * 32 + nt * 8 + lc * 2;
        float bm0 = b_mu[col],  bm1 = b_mu[col + 1];
        float bs0 = softplusf(b_sigma[col]), bs1 = softplusf(b_sigma[col + 1]);
#pragma unroll
        for (int mt = 0; mt < 4; mt++) {
            int row = m0 + wm * 64 + mt * 16 + lr;
            float2 v;
            v.x = acc1[mt][nt][0] + bm0; v.y = acc1[mt][nt][1] + bm1;
            *(float2*)(o1 + (size_t)row * SZ + col) = v;
            v.x = acc1[mt][nt][2] + bm0; v.y = acc1[mt][nt][3] + bm1;
            *(float2*)(o1 + (size_t)(row + 8) * SZ + col) = v;
            v.x = acc2[mt][nt][0] + bs0; v.y = acc2[mt][nt][1] + bs1;
            *(float2*)(o2 + (size_t)row * SZ + col) = v;
            v.x = acc2[mt][nt][2] + bs0; v.y = acc2[mt][nt][3] + bs1;
            *(float2*)(o2 + (size_t)(row + 8) * SZ + col) = v;
        }
    }
}

// ---------------- launch -----------------------------------------------------
extern "C" void kernel_launch(void* const* d_in, const int* in_sizes, int n_in,
                              void* d_out, int out_size) {
    const float* mu_in   = (const float*)d_in[0];
    // d_in[1] = sigma_in : unused by the reference outputs
    const float* w_mu    = (const float*)d_in[2];
    const float* w_sigma = (const float*)d_in[3];
    const float* b_mu    = (const float*)d_in[4];
    const float* b_sigma = (const float*)d_in[5];
    float* out = (float*)d_out;

    cudaFuncSetAttribute(gemm_tf32, cudaFuncAttributeMaxDynamicSharedMemorySize,
                         SMEM_TOTAL);

    init_kernel<<<1, 32>>>();
    prep_w<<<dim3(128, 128), dim3(32, 8)>>>(w_mu, w_sigma);
    prep_a<<<4096, 256>>>(mu_in);
    gemm_tf32<<<dim3(SZ / BN, SZ / BM), 256, SMEM_TOTAL>>>(b_mu, b_sigma, out);
    finalize_kl<<<1, 1>>>(out);
}

// round 7
// speedup vs baseline: 1.3986x; 1.0262x over previous
#include <cuda_runtime.h>
#include <math.h>
#include <stdint.h>

#define SZ 4096
#define NW (SZ*SZ)

// ---------------- scratch (static __device__, no runtime alloc) -------------
__device__ float  g_a[NW];     // tf32-rounded mu_in         [B][K]
__device__ float  g_w1t[NW];   // tf32-rounded w_mu^T        [N][K]
__device__ float  g_w2t[NW];   // tf32-rounded sp(w_sigma)^T [N][K]
__device__ double g_sums[3];   // [0]=sum log(sp) [1]=sum sp [2]=sum |w_mu|

__device__ __forceinline__ float softplusf(float x) {
    return x > 20.0f ? x : log1pf(expf(x));
}
__device__ __forceinline__ float tf32_rn(float x) {
    float y; asm("cvt.rna.tf32.f32 %0, %1;" : "=f"(y) : "f"(x)); return y;
}
__device__ __forceinline__ void cp16(uint32_t dst, const float* src) {
    asm volatile("cp.async.cg.shared.global [%0], [%1], 16;"
                 :: "r"(dst), "l"(__cvta_generic_to_global(src)));
}
__device__ __forceinline__ uint32_t smem_u32(const void* p) {
    uint32_t a;
    asm("{ .reg .u64 t; cvta.to.shared.u64 t, %1; cvt.u32.u64 %0, t; }"
        : "=r"(a) : "l"(p));
    return a;
}

#define LDSM4(r0, r1, r2, r3, addr) \
    asm volatile("ldmatrix.sync.aligned.m8n8.x4.shared.b16 {%0,%1,%2,%3}, [%4];" \
        : "=r"(r0), "=r"(r1), "=r"(r2), "=r"(r3) : "r"(addr))

#define MMA_TF32U(d, a0, a1, a2, a3, b0, b1) \
    asm volatile( \
        "mma.sync.aligned.m16n8k8.row.col.f32.tf32.tf32.f32 " \
        "{%0,%1,%2,%3}, {%4,%5,%6,%7}, {%8,%9}, {%0,%1,%2,%3};" \
        : "+f"((d)[0]), "+f"((d)[1]), "+f"((d)[2]), "+f"((d)[3]) \
        : "r"(a0), "r"(a1), "r"(a2), "r"(a3), "r"(b0), "r"(b1))

// ---------------- prep kernels ----------------------------------------------
__global__ void init_kernel() {
    if (threadIdx.x < 3) g_sums[threadIdx.x] = 0.0;
}

__global__ void prep_w(const float* __restrict__ w_mu,
                       const float* __restrict__ w_sigma) {
    __shared__ float t1[32][33];
    __shared__ float t2[32][33];
    __shared__ float red[3][256];
    const int bx = blockIdx.x * 32;   // n
    const int by = blockIdx.y * 32;   // k
    const int tx = threadIdx.x, ty = threadIdx.y;
    const int tid = ty * 32 + tx;

    float s_log = 0.f, s_sp = 0.f, s_abs = 0.f;
#pragma unroll
    for (int i = 0; i < 4; i++) {
        int k = by + ty + i * 8;
        int n = bx + tx;
        float wm = w_mu[(size_t)k * SZ + n];
        float ws = w_sigma[(size_t)k * SZ + n];
        float sp = softplusf(ws);
        s_log += logf(sp);
        s_sp  += sp;
        s_abs += fabsf(wm);
        t1[ty + i * 8][tx] = tf32_rn(wm);
        t2[ty + i * 8][tx] = tf32_rn(sp);
    }
    __syncthreads();
#pragma unroll
    for (int i = 0; i < 4; i++) {
        int n = bx + ty + i * 8;
        int k = by + tx;
        g_w1t[(size_t)n * SZ + k] = t1[tx][ty + i * 8];
        g_w2t[(size_t)n * SZ + k] = t2[tx][ty + i * 8];
    }

    red[0][tid] = s_log; red[1][tid] = s_sp; red[2][tid] = s_abs;
    __syncthreads();
    for (int off = 128; off > 0; off >>= 1) {
        if (tid < off) {
            red[0][tid] += red[0][tid + off];
            red[1][tid] += red[1][tid + off];
            red[2][tid] += red[2][tid + off];
        }
        __syncthreads();
    }
    if (tid == 0) {
        atomicAdd(&g_sums[0], (double)red[0][0]);
        atomicAdd(&g_sums[1], (double)red[1][0]);
        atomicAdd(&g_sums[2], (double)red[2][0]);
    }
}

__global__ void prep_a(const float* __restrict__ mu) {
    const float4* m4 = (const float4*)mu;
    float4* a4 = (float4*)g_a;
    int stride = gridDim.x * blockDim.x;
    for (int i = blockIdx.x * blockDim.x + threadIdx.x; i < NW / 4; i += stride) {
        float4 x = m4[i];
        float4 a;
        a.x = tf32_rn(x.x); a.y = tf32_rn(x.y);
        a.z = tf32_rn(x.z); a.w = tf32_rn(x.w);
        a4[i] = a;
    }
}

__global__ void finalize_kl(float* __restrict__ out) {
    double mean_log = g_sums[0] / (double)NW;
    double mean_sp  = g_sums[1] / (double)NW;
    double kl = -0.5 * ((double)SZ * mean_log - g_sums[2] - (double)SZ * mean_sp);
    out[(size_t)2 * SZ * SZ] = (float)kl;
}

// ---------------- main dual GEMM (mma.sync tf32 + ldmatrix, 2 CTA/SM) --------
// CTA: 128x64, both paths. 256 threads, 8 warps (4m x 2n), warp tile 32x32.
#define BM 128
#define BN 64
#define BK 32
#define STAGES 3
#define NCHUNK (SZ / BK)       // 128
#define PITCH 36               // floats per smem row (conflict-free)

#define A_BYTES  (128 * PITCH * 4)          // 18432
#define W_BYTES  (64 * PITCH * 4)           // 9216
#define STAGE_BYTES (A_BYTES + 2 * W_BYTES) // 36864
#define SMEM_TOTAL (STAGES * STAGE_BYTES)   // 110592

__global__ __launch_bounds__(256, 2)
void gemm_tf32(const float* __restrict__ b_mu,
               const float* __restrict__ b_sigma,
               float* __restrict__ out) {
    extern __shared__ char smem[];
    const uint32_t sb = smem_u32(smem);

    const int tid = threadIdx.x;
    const int wid = tid >> 5;
    const int lid = tid & 31;
    const int lr  = lid >> 2;     // 0..7
    const int lc  = lid & 3;      // 0..3
    const int wm  = wid >> 1;     // 0..3  (m-block, 32 rows)
    const int wn  = wid & 1;      // 0..1  (n-block, 32 cols)
    const int m0 = blockIdx.y * BM;
    const int n0 = blockIdx.x * BN;

    // ldmatrix per-lane source offsets (bytes)
    const int lrow = lid & 7;
    const int lmat = lid >> 3;
    // A x4: mats {rows0-7 klo, rows8-15 klo, rows0-7 khi, rows8-15 khi}
    const uint32_t offA = (uint32_t)((((lmat & 1) * 8 + lrow) * PITCH + (lmat >> 1) * 4) * 4);
    // W x4: mats {nblk0 klo, nblk0 khi, nblk1 klo, nblk1 khi}
    const uint32_t offW = (uint32_t)((((lmat >> 1) * 8 + lrow) * PITCH + (lmat & 1) * 4) * 4);

    uint32_t relA[2], relW[2];
#pragma unroll
    for (int mt = 0; mt < 2; mt++)
        relA[mt] = (uint32_t)((wm * 32 + mt * 16) * PITCH * 4) + offA;
#pragma unroll
    for (int ntp = 0; ntp < 2; ntp++)
        relW[ntp] = (uint32_t)((wn * 32 + ntp * 16) * PITCH * 4) + offW;

    float acc1[2][4][4];
    float acc2[2][4][4];
#pragma unroll
    for (int mt = 0; mt < 2; mt++)
#pragma unroll
        for (int nt = 0; nt < 4; nt++)
#pragma unroll
            for (int q = 0; q < 4; q++) { acc1[mt][nt][q] = 0.f; acc2[mt][nt][q] = 0.f; }

    // Stage loader: 8 x 16B cp.async per thread (A: 4, W1: 2, W2: 2)
    auto load_stage = [&](int chunk, int s) {
        const int k0 = chunk * BK;
        const uint32_t base = sb + s * STAGE_BYTES;
#pragma unroll
        for (int i = 0; i < 4; i++) {           // A: 128 rows x 8 c4
            int f = tid + i * 256;
            int r = f >> 3, c4 = f & 7;
            uint32_t doff = (uint32_t)(r * (PITCH * 4) + c4 * 16);
            cp16(base + doff, g_a + (size_t)(m0 + r) * SZ + k0 + c4 * 4);
        }
#pragma unroll
        for (int i = 0; i < 2; i++) {           // W1, W2: 64 rows x 8 c4
            int f = tid + i * 256;
            int r = f >> 3, c4 = f & 7;
            uint32_t doff = (uint32_t)(r * (PITCH * 4) + c4 * 16);
            size_t woff = (size_t)(n0 + r) * SZ + k0 + c4 * 4;
            cp16(base + A_BYTES + doff,           g_w1t + woff);
            cp16(base + A_BYTES + W_BYTES + doff, g_w2t + woff);
        }
        asm volatile("cp.async.commit_group;" ::: "memory");
    };

    load_stage(0, 0);
    load_stage(1, 1);

    for (int c = 0; c < NCHUNK; c++) {
        const int s = c % STAGES;
        asm volatile("cp.async.wait_group 1;" ::: "memory");
        __syncthreads();
        if (c + 2 < NCHUNK) load_stage(c + 2, (c + 2) % STAGES);
        else asm volatile("cp.async.commit_group;" ::: "memory");

        const uint32_t stA  = sb + s * STAGE_BYTES;
        const uint32_t stW1 = stA + A_BYTES;
        const uint32_t stW2 = stA + A_BYTES + W_BYTES;

#pragma unroll
        for (int ks = 0; ks < BK / 8; ks++) {
            const uint32_t kb = (uint32_t)(ks * 32);
            uint32_t af[2][4], a2f[2][4];
#pragma unroll
            for (int mt = 0; mt < 2; mt++) {
                LDSM4(af[mt][0], af[mt][1], af[mt][2], af[mt][3], stA + relA[mt] + kb);
#pragma unroll
                for (int q = 0; q < 4; q++) {
                    float v = __uint_as_float(af[mt][q]);
                    a2f[mt][q] = __float_as_uint(tf32_rn(v * v));
                }
            }
            uint32_t w1f[2][4], w2f[2][4];
#pragma unroll
            for (int ntp = 0; ntp < 2; ntp++) {
                LDSM4(w1f[ntp][0], w1f[ntp][1], w1f[ntp][2], w1f[ntp][3],
                      stW1 + relW[ntp] + kb);
                LDSM4(w2f[ntp][0], w2f[ntp][1], w2f[ntp][2], w2f[ntp][3],
                      stW2 + relW[ntp] + kb);
            }
#pragma unroll
            for (int ntp = 0; ntp < 2; ntp++) {
#pragma unroll
                for (int h = 0; h < 2; h++) {
                    const int nt = ntp * 2 + h;
                    const uint32_t b0 = w1f[ntp][h * 2], b1 = w1f[ntp][h * 2 + 1];
#pragma unroll
                    for (int mt = 0; mt < 2; mt++)
                        MMA_TF32U(acc1[mt][nt], af[mt][0], af[mt][1], af[mt][2],
                                  af[mt][3], b0, b1);
                    const uint32_t c0 = w2f[ntp][h * 2], c1 = w2f[ntp][h * 2 + 1];
#pragma unroll
                    for (int mt = 0; mt < 2; mt++)
                        MMA_TF32U(acc2[mt][nt], a2f[mt][0], a2f[mt][1], a2f[mt][2],
                                  a2f[mt][3], c0, c1);
                }
            }
        }
    }

    // ---------------- epilogue ----------------
    float* o1 = out;
    float* o2 = out + (size_t)SZ * SZ;
#pragma unroll
    for (int nt = 0; nt < 4; nt++) {
        int col = n0 + wn * 32 + nt * 8 + lc * 2;
        float bm0 = b_mu[col],  bm1 = b_mu[col + 1];
        float bs0 = softplusf(b_sigma[col]), bs1 = softplusf(b_sigma[col + 1]);
#pragma unroll
        for (int mt = 0; mt < 2; mt++) {
            int row = m0 + wm * 32 + mt * 16 + lr;
            float2 v;
            v.x = acc1[mt][nt][0] + bm0; v.y = acc1[mt][nt][1] + bm1;
            *(float2*)(o1 + (size_t)row * SZ + col) = v;
            v.x = acc1[mt][nt][2] + bm0; v.y = acc1[mt][nt][3] + bm1;
            *(float2*)(o1 + (size_t)(row + 8) * SZ + col) = v;
            v.x = acc2[mt][nt][0] + bs0; v.y = acc2[mt][nt][1] + bs1;
            *(float2*)(o2 + (size_t)row * SZ + col) = v;
            v.x = acc2[mt][nt][2] + bs0; v.y = acc2[mt][nt][3] + bs1;
            *(float2*)(o2 + (size_t)(row + 8) * SZ + col) = v;
        }
    }
}

// ---------------- launch -----------------------------------------------------
extern "C" void kernel_launch(void* const* d_in, const int* in_sizes, int n_in,
                              void* d_out, int out_size) {
    const float* mu_in   = (const float*)d_in[0];
    // d_in[1] = sigma_in : unused by the reference outputs
    const float* w_mu    = (const float*)d_in[2];
    const float* w_sigma = (const float*)d_in[3];
    const float* b_mu    = (const float*)d_in[4];
    const float* b_sigma = (const float*)d_in[5];
    float* out = (float*)d_out;

    cudaFuncSetAttribute(gemm_tf32, cudaFuncAttributeMaxDynamicSharedMemorySize,
                         SMEM_TOTAL);

    init_kernel<<<1, 32>>>();
    prep_w<<<dim3(128, 128), dim3(32, 8)>>>(w_mu, w_sigma);
    prep_a<<<4096, 256>>>(mu_in);
    gemm_tf32<<<dim3(SZ / BN, SZ / BM), 256, SMEM_TOTAL>>>(b_mu, b_sigma, out);
    finalize_kl<<<1, 1>>>(out);
}

// round 8
// speedup vs baseline: 1.4892x; 1.0648x over previous
#include <cuda_runtime.h>
#include <cuda_bf16.h>
#include <math.h>
#include <stdint.h>

#define SZ 4096
#define NW (SZ*SZ)

// ---------------- scratch (static __device__, no runtime alloc) -------------
__device__ __align__(16) float         g_a[NW];    // tf32-rounded mu_in [B][K]
__device__ __align__(16) float         g_w1t[NW];  // tf32-rounded w_mu^T [N][K]
__device__ __align__(16) __nv_bfloat16 g_a2h[NW];  // bf16(mu^2)        [B][K]
__device__ __align__(16) __nv_bfloat16 g_w2h[NW];  // bf16(sp(w_sig))^T [N][K]
__device__ double g_sums[3];   // [0]=sum log(sp) [1]=sum sp [2]=sum |w_mu|

__device__ __forceinline__ float softplusf(float x) {
    return x > 20.0f ? x : log1pf(expf(x));
}
__device__ __forceinline__ float tf32_rn(float x) {
    float y; asm("cvt.rna.tf32.f32 %0, %1;" : "=f"(y) : "f"(x)); return y;
}
__device__ __forceinline__ void cp16(uint32_t dst, const void* src) {
    asm volatile("cp.async.cg.shared.global [%0], [%1], 16;"
                 :: "r"(dst), "l"(__cvta_generic_to_global(src)));
}
__device__ __forceinline__ uint32_t smem_u32(const void* p) {
    uint32_t a;
    asm("{ .reg .u64 t; cvta.to.shared.u64 t, %1; cvt.u32.u64 %0, t; }"
        : "=r"(a) : "l"(p));
    return a;
}

#define LDSM4(r0, r1, r2, r3, addr) \
    asm volatile("ldmatrix.sync.aligned.m8n8.x4.shared.b16 {%0,%1,%2,%3}, [%4];" \
        : "=r"(r0), "=r"(r1), "=r"(r2), "=r"(r3) : "r"(addr))

#define MMA_TF32U(d, a0, a1, a2, a3, b0, b1) \
    asm volatile( \
        "mma.sync.aligned.m16n8k8.row.col.f32.tf32.tf32.f32 " \
        "{%0,%1,%2,%3}, {%4,%5,%6,%7}, {%8,%9}, {%0,%1,%2,%3};" \
        : "+f"((d)[0]), "+f"((d)[1]), "+f"((d)[2]), "+f"((d)[3]) \
        : "r"(a0), "r"(a1), "r"(a2), "r"(a3), "r"(b0), "r"(b1))

#define MMA_BF16(d, a0, a1, a2, a3, b0, b1) \
    asm volatile( \
        "mma.sync.aligned.m16n8k16.row.col.f32.bf16.bf16.f32 " \
        "{%0,%1,%2,%3}, {%4,%5,%6,%7}, {%8,%9}, {%0,%1,%2,%3};" \
        : "+f"((d)[0]), "+f"((d)[1]), "+f"((d)[2]), "+f"((d)[3]) \
        : "r"(a0), "r"(a1), "r"(a2), "r"(a3), "r"(b0), "r"(b1))

// ---------------- prep kernels ----------------------------------------------
__global__ void init_kernel() {
    if (threadIdx.x < 3) g_sums[threadIdx.x] = 0.0;
}

__global__ void prep_w(const float* __restrict__ w_mu,
                       const float* __restrict__ w_sigma) {
    __shared__ float t1[32][33];
    __shared__ float t2[32][33];
    __shared__ float red[3][256];
    const int bx = blockIdx.x * 32;   // n
    const int by = blockIdx.y * 32;   // k
    const int tx = threadIdx.x, ty = threadIdx.y;
    const int tid = ty * 32 + tx;

    float s_log = 0.f, s_sp = 0.f, s_abs = 0.f;
#pragma unroll
    for (int i = 0; i < 4; i++) {
        int k = by + ty + i * 8;
        int n = bx + tx;
        float wm = w_mu[(size_t)k * SZ + n];
        float ws = w_sigma[(size_t)k * SZ + n];
        float sp = softplusf(ws);
        s_log += logf(sp);
        s_sp  += sp;
        s_abs += fabsf(wm);
        t1[ty + i * 8][tx] = tf32_rn(wm);
        t2[ty + i * 8][tx] = sp;          // full fp32; bf16-rounded on store
    }
    __syncthreads();
#pragma unroll
    for (int i = 0; i < 4; i++) {
        int n = bx + ty + i * 8;
        int k = by + tx;
        g_w1t[(size_t)n * SZ + k] = t1[tx][ty + i * 8];
        g_w2h[(size_t)n * SZ + k] = __float2bfloat16_rn(t2[tx][ty + i * 8]);
    }

    red[0][tid] = s_log; red[1][tid] = s_sp; red[2][tid] = s_abs;
    __syncthreads();
    for (int off = 128; off > 0; off >>= 1) {
        if (tid < off) {
            red[0][tid] += red[0][tid + off];
            red[1][tid] += red[1][tid + off];
            red[2][tid] += red[2][tid + off];
        }
        __syncthreads();
    }
    if (tid == 0) {
        atomicAdd(&g_sums[0], (double)red[0][0]);
        atomicAdd(&g_sums[1], (double)red[1][0]);
        atomicAdd(&g_sums[2], (double)red[2][0]);
    }
}

__global__ void prep_a(const float* __restrict__ mu) {
    const float4* m4 = (const float4*)mu;
    float4* a4 = (float4*)g_a;
    __nv_bfloat162* a2h2 = (__nv_bfloat162*)g_a2h;
    int stride = gridDim.x * blockDim.x;
    for (int i = blockIdx.x * blockDim.x + threadIdx.x; i < NW / 4; i += stride) {
        float4 x = m4[i];
        float4 a;
        a.x = tf32_rn(x.x); a.y = tf32_rn(x.y);
        a.z = tf32_rn(x.z); a.w = tf32_rn(x.w);
        a4[i] = a;
        float2 p0 = make_float2(x.x * x.x, x.y * x.y);
        float2 p1 = make_float2(x.z * x.z, x.w * x.w);
        a2h2[i * 2]     = __float22bfloat162_rn(p0);
        a2h2[i * 2 + 1] = __float22bfloat162_rn(p1);
    }
}

__global__ void finalize_kl(float* __restrict__ out) {
    double mean_log = g_sums[0] / (double)NW;
    double mean_sp  = g_sums[1] / (double)NW;
    double kl = -0.5 * ((double)SZ * mean_log - g_sums[2] - (double)SZ * mean_sp);
    out[(size_t)2 * SZ * SZ] = (float)kl;
}

// ---------------- main dual GEMM: mu=tf32 k8, Sigma=bf16 k16 -----------------
// CTA: 128x64, 256 threads, 8 warps (4m x 2n), warp tile 32x32, 2 CTA/SM.
#define BM 128
#define BN 64
#define BK 32
#define NCHUNK (SZ / BK)       // 128
#define PITCH 36               // floats per tf32 smem row
#define PITCH_H 80             // bytes per bf16 smem row (conflict-free: 20r%32)

#define A_BYTES   (128 * PITCH * 4)                 // 18432
#define W1_BYTES  (64 * PITCH * 4)                  // 9216
#define A2_BYTES  (128 * PITCH_H)                   // 10240
#define W2_BYTES  (64 * PITCH_H)                    // 5120
#define OFF_W1    A_BYTES
#define OFF_A2    (A_BYTES + W1_BYTES)
#define OFF_W2    (A_BYTES + W1_BYTES + A2_BYTES)
#define STAGE_BYTES (A_BYTES + W1_BYTES + A2_BYTES + W2_BYTES)  // 43008
#define SMEM_TOTAL (2 * STAGE_BYTES)                            // 86016

__global__ __launch_bounds__(256, 2)
void gemm_dual(const float* __restrict__ b_mu,
               const float* __restrict__ b_sigma,
               float* __restrict__ out) {
    extern __shared__ char smem[];
    const uint32_t sb = smem_u32(smem);

    const int tid = threadIdx.x;
    const int wid = tid >> 5;
    const int lid = tid & 31;
    const int lr  = lid >> 2;     // 0..7
    const int lc  = lid & 3;      // 0..3
    const int wm  = wid >> 1;     // 0..3
    const int wn  = wid & 1;      // 0..1
    const int m0 = blockIdx.y * BM;
    const int n0 = blockIdx.x * BN;

    const int lrow = lid & 7;
    const int lmat = lid >> 3;
    // tf32 tiles (PITCH floats): A mats {mlo-klo, mhi-klo, mlo-khi, mhi-khi}
    const uint32_t offA = (uint32_t)((((lmat & 1) * 8 + lrow) * PITCH + (lmat >> 1) * 4) * 4);
    const uint32_t offW = (uint32_t)((((lmat >> 1) * 8 + lrow) * PITCH + (lmat & 1) * 4) * 4);
    // bf16 tiles (PITCH_H bytes): same mat orders, 16B k-units
    const uint32_t offA2 = (uint32_t)(((lmat & 1) * 8 + lrow) * PITCH_H + (lmat >> 1) * 16);
    const uint32_t offW2 = (uint32_t)(((lmat >> 1) * 8 + lrow) * PITCH_H + (lmat & 1) * 16);

    uint32_t relA[2], relW[2], relA2[2], relW2[2];
#pragma unroll
    for (int mt = 0; mt < 2; mt++) {
        relA[mt]  = (uint32_t)((wm * 32 + mt * 16) * PITCH * 4) + offA;
        relA2[mt] = (uint32_t)((wm * 32 + mt * 16) * PITCH_H) + offA2;
    }
#pragma unroll
    for (int ntp = 0; ntp < 2; ntp++) {
        relW[ntp]  = (uint32_t)((wn * 32 + ntp * 16) * PITCH * 4) + offW;
        relW2[ntp] = (uint32_t)((wn * 32 + ntp * 16) * PITCH_H) + offW2;
    }

    float acc1[2][4][4];
    float acc2[2][4][4];
#pragma unroll
    for (int mt = 0; mt < 2; mt++)
#pragma unroll
        for (int nt = 0; nt < 4; nt++)
#pragma unroll
            for (int q = 0; q < 4; q++) { acc1[mt][nt][q] = 0.f; acc2[mt][nt][q] = 0.f; }

    // Stage loader: 9 x 16B cp.async per thread
    auto load_stage = [&](int chunk, int s) {
        const int k0 = chunk * BK;
        const uint32_t base = sb + s * STAGE_BYTES;
#pragma unroll
        for (int i = 0; i < 4; i++) {           // A tf32: 128 rows x 8 c4
            int f = tid + i * 256;
            int r = f >> 3, c4 = f & 7;
            cp16(base + (uint32_t)(r * (PITCH * 4) + c4 * 16),
                 g_a + (size_t)(m0 + r) * SZ + k0 + c4 * 4);
        }
#pragma unroll
        for (int i = 0; i < 2; i++) {           // W1 tf32: 64 rows x 8 c4
            int f = tid + i * 256;
            int r = f >> 3, c4 = f & 7;
            cp16(base + OFF_W1 + (uint32_t)(r * (PITCH * 4) + c4 * 16),
                 g_w1t + (size_t)(n0 + r) * SZ + k0 + c4 * 4);
        }
#pragma unroll
        for (int i = 0; i < 2; i++) {           // A2h bf16: 128 rows x 4 u16
            int f = tid + i * 256;
            int r = f >> 2, u = f & 3;
            cp16(base + OFF_A2 + (uint32_t)(r * PITCH_H + u * 16),
                 (const char*)g_a2h + ((size_t)(m0 + r) * SZ + k0) * 2 + u * 16);
        }
        {                                        // W2h bf16: 64 rows x 4 u16
            int r = tid >> 2, u = tid & 3;
            cp16(base + OFF_W2 + (uint32_t)(r * PITCH_H + u * 16),
                 (const char*)g_w2h + ((size_t)(n0 + r) * SZ + k0) * 2 + u * 16);
        }
        asm volatile("cp.async.commit_group;" ::: "memory");
    };

    load_stage(0, 0);

    for (int c = 0; c < NCHUNK; c++) {
        const int s = c & 1;
        asm volatile("cp.async.wait_group 0;" ::: "memory");
        __syncthreads();
        if (c + 1 < NCHUNK) load_stage(c + 1, s ^ 1);

        const uint32_t stA  = sb + s * STAGE_BYTES;
        const uint32_t stW1 = stA + OFF_W1;
        const uint32_t stA2 = stA + OFF_A2;
        const uint32_t stW2 = stA + OFF_W2;

#pragma unroll
        for (int j = 0; j < 2; j++) {
            // ---- mu path: tf32 k8, ks = 2j, 2j+1 ----
#pragma unroll
            for (int ksub = 0; ksub < 2; ksub++) {
                const uint32_t kb = (uint32_t)((j * 2 + ksub) * 32);
                uint32_t af[2][4];
#pragma unroll
                for (int mt = 0; mt < 2; mt++)
                    LDSM4(af[mt][0], af[mt][1], af[mt][2], af[mt][3],
                          stA + relA[mt] + kb);
#pragma unroll
                for (int ntp = 0; ntp < 2; ntp++) {
                    uint32_t wf[4];
                    LDSM4(wf[0], wf[1], wf[2], wf[3], stW1 + relW[ntp] + kb);
#pragma unroll
                    for (int h = 0; h < 2; h++) {
                        const int nt = ntp * 2 + h;
#pragma unroll
                        for (int mt = 0; mt < 2; mt++)
                            MMA_TF32U(acc1[mt][nt], af[mt][0], af[mt][1],
                                      af[mt][2], af[mt][3],
                                      wf[h * 2], wf[h * 2 + 1]);
                    }
                }
            }
            // ---- Sigma path: bf16 k16, kstep j ----
            {
                const uint32_t kb = (uint32_t)(j * 32);   // 2 16B units
                uint32_t a2f[2][4];
#pragma unroll
                for (int mt = 0; mt < 2; mt++)
                    LDSM4(a2f[mt][0], a2f[mt][1], a2f[mt][2], a2f[mt][3],
                          stA2 + relA2[mt] + kb);
#pragma unroll
                for (int ntp = 0; ntp < 2; ntp++) {
                    uint32_t wf[4];
                    LDSM4(wf[0], wf[1], wf[2], wf[3], stW2 + relW2[ntp] + kb);
#pragma unroll
                    for (int nb = 0; nb < 2; nb++) {
                        const int nt = ntp * 2 + nb;
#pragma unroll
                        for (int mt = 0; mt < 2; mt++)
                            MMA_BF16(acc2[mt][nt], a2f[mt][0], a2f[mt][1],
                                     a2f[mt][2], a2f[mt][3],
                                     wf[nb * 2], wf[nb * 2 + 1]);
                    }
                }
            }
        }
    }

    // ---------------- epilogue ----------------
    float* o1 = out;
    float* o2 = out + (size_t)SZ * SZ;
#pragma unroll
    for (int nt = 0; nt < 4; nt++) {
        int col = n0 + wn * 32 + nt * 8 + lc * 2;
        float bm0 = b_mu[col],  bm1 = b_mu[col + 1];
        float bs0 = softplusf(b_sigma[col]), bs1 = softplusf(b_sigma[col + 1]);
#pragma unroll
        for (int mt = 0; mt < 2; mt++) {
            int row = m0 + wm * 32 + mt * 16 + lr;
            float2 v;
            v.x = acc1[mt][nt][0] + bm0; v.y = acc1[mt][nt][1] + bm1;
            *(float2*)(o1 + (size_t)row * SZ + col) = v;
            v.x = acc1[mt][nt][2] + bm0; v.y = acc1[mt][nt][3] + bm1;
            *(float2*)(o1 + (size_t)(row + 8) * SZ + col) = v;
            v.x = acc2[mt][nt][0] + bs0; v.y = acc2[mt][nt][1] + bs1;
            *(float2*)(o2 + (size_t)row * SZ + col) = v;
            v.x = acc2[mt][nt][2] + bs0; v.y = acc2[mt][nt][3] + bs1;
            *(float2*)(o2 + (size_t)(row + 8) * SZ + col) = v;
        }
    }
}

// ---------------- launch -----------------------------------------------------
extern "C" void kernel_launch(void* const* d_in, const int* in_sizes, int n_in,
                              void* d_out, int out_size) {
    const float* mu_in   = (const float*)d_in[0];
    // d_in[1] = sigma_in : unused by the reference outputs
    const float* w_mu    = (const float*)d_in[2];
    const float* w_sigma = (const float*)d_in[3];
    const float* b_mu    = (const float*)d_in[4];
    const float* b_sigma = (const float*)d_in[5];
    float* out = (float*)d_out;

    cudaFuncSetAttribute(gemm_dual, cudaFuncAttributeMaxDynamicSharedMemorySize,
                         SMEM_TOTAL);

    init_kernel<<<1, 32>>>();
    prep_w<<<dim3(128, 128), dim3(32, 8)>>>(w_mu, w_sigma);
    prep_a<<<4096, 256>>>(mu_in);
    gemm_dual<<<dim3(SZ / BN, SZ / BM), 256, SMEM_TOTAL>>>(b_mu, b_sigma, out);
    finalize_kl<<<1, 1>>>(out);
}

// round 9
// speedup vs baseline: 1.8772x; 1.2606x over previous
#include <cuda_runtime.h>
#include <cuda_bf16.h>
#include <math.h>
#include <stdint.h>

#define SZ 4096
#define NW (SZ*SZ)

// ---------------- scratch (static __device__, no runtime alloc) -------------
__device__ __align__(16) float         g_a[NW];    // tf32-rounded mu_in [B][K]
__device__ __align__(16) float         g_w1t[NW];  // tf32-rounded w_mu^T [N][K]
__device__ __align__(16) __nv_bfloat16 g_a2h[NW];  // bf16(mu^2)        [B][K]
__device__ __align__(16) __nv_bfloat16 g_w2h[NW];  // bf16(sp(w_sig))^T [N][K]
__device__ double g_sums[3];   // [0]=sum log(sp) [1]=sum sp [2]=sum |w_mu|

__device__ __forceinline__ float softplusf(float x) {
    return x > 20.0f ? x : log1pf(expf(x));
}
__device__ __forceinline__ float tf32_rn(float x) {
    float y; asm("cvt.rna.tf32.f32 %0, %1;" : "=f"(y) : "f"(x)); return y;
}
__device__ __forceinline__ void cp16(uint32_t dst, const void* src) {
    asm volatile("cp.async.cg.shared.global [%0], [%1], 16;"
                 :: "r"(dst), "l"(__cvta_generic_to_global(src)));
}
__device__ __forceinline__ uint32_t smem_u32(const void* p) {
    uint32_t a;
    asm("{ .reg .u64 t; cvta.to.shared.u64 t, %1; cvt.u32.u64 %0, t; }"
        : "=r"(a) : "l"(p));
    return a;
}
__device__ __forceinline__ uint32_t swz128(uint32_t off) {
    return off ^ ((off >> 3) & 0x70);
}
__device__ __forceinline__ uint32_t swz64(uint32_t off) {
    return off ^ ((off >> 3) & 0x30);
}

#define LDSM4(r0, r1, r2, r3, addr) \
    asm volatile("ldmatrix.sync.aligned.m8n8.x4.shared.b16 {%0,%1,%2,%3}, [%4];" \
        : "=r"(r0), "=r"(r1), "=r"(r2), "=r"(r3) : "r"(addr))

#define MMA_TF32U(d, a0, a1, a2, a3, b0, b1) \
    asm volatile( \
        "mma.sync.aligned.m16n8k8.row.col.f32.tf32.tf32.f32 " \
        "{%0,%1,%2,%3}, {%4,%5,%6,%7}, {%8,%9}, {%0,%1,%2,%3};" \
        : "+f"((d)[0]), "+f"((d)[1]), "+f"((d)[2]), "+f"((d)[3]) \
        : "r"(a0), "r"(a1), "r"(a2), "r"(a3), "r"(b0), "r"(b1))

#define MMA_BF16(d, a0, a1, a2, a3, b0, b1) \
    asm volatile( \
        "mma.sync.aligned.m16n8k16.row.col.f32.bf16.bf16.f32 " \
        "{%0,%1,%2,%3}, {%4,%5,%6,%7}, {%8,%9}, {%0,%1,%2,%3};" \
        : "+f"((d)[0]), "+f"((d)[1]), "+f"((d)[2]), "+f"((d)[3]) \
        : "r"(a0), "r"(a1), "r"(a2), "r"(a3), "r"(b0), "r"(b1))

// ---------------- prep kernels ----------------------------------------------
__global__ void init_kernel() {
    if (threadIdx.x < 3) g_sums[threadIdx.x] = 0.0;
}

__global__ void prep_w(const float* __restrict__ w_mu,
                       const float* __restrict__ w_sigma) {
    __shared__ float t1[32][33];
    __shared__ float t2[32][33];
    __shared__ float red[3][256];
    const int bx = blockIdx.x * 32;   // n
    const int by = blockIdx.y * 32;   // k
    const int tx = threadIdx.x, ty = threadIdx.y;
    const int tid = ty * 32 + tx;

    float s_log = 0.f, s_sp = 0.f, s_abs = 0.f;
#pragma unroll
    for (int i = 0; i < 4; i++) {
        int k = by + ty + i * 8;
        int n = bx + tx;
        float wm = w_mu[(size_t)k * SZ + n];
        float ws = w_sigma[(size_t)k * SZ + n];
        float sp = softplusf(ws);
        s_log += logf(sp);
        s_sp  += sp;
        s_abs += fabsf(wm);
        t1[ty + i * 8][tx] = tf32_rn(wm);
        t2[ty + i * 8][tx] = sp;
    }
    __syncthreads();
#pragma unroll
    for (int i = 0; i < 4; i++) {
        int n = bx + ty + i * 8;
        int k = by + tx;
        g_w1t[(size_t)n * SZ + k] = t1[tx][ty + i * 8];
        g_w2h[(size_t)n * SZ + k] = __float2bfloat16_rn(t2[tx][ty + i * 8]);
    }

    red[0][tid] = s_log; red[1][tid] = s_sp; red[2][tid] = s_abs;
    __syncthreads();
    for (int off = 128; off > 0; off >>= 1) {
        if (tid < off) {
            red[0][tid] += red[0][tid + off];
            red[1][tid] += red[1][tid + off];
            red[2][tid] += red[2][tid + off];
        }
        __syncthreads();
    }
    if (tid == 0) {
        atomicAdd(&g_sums[0], (double)red[0][0]);
        atomicAdd(&g_sums[1], (double)red[1][0]);
        atomicAdd(&g_sums[2], (double)red[2][0]);
    }
}

__global__ void prep_a(const float* __restrict__ mu) {
    const float4* m4 = (const float4*)mu;
    float4* a4 = (float4*)g_a;
    __nv_bfloat162* a2h2 = (__nv_bfloat162*)g_a2h;
    int stride = gridDim.x * blockDim.x;
    for (int i = blockIdx.x * blockDim.x + threadIdx.x; i < NW / 4; i += stride) {
        float4 x = m4[i];
        float4 a;
        a.x = tf32_rn(x.x); a.y = tf32_rn(x.y);
        a.z = tf32_rn(x.z); a.w = tf32_rn(x.w);
        a4[i] = a;
        float2 p0 = make_float2(x.x * x.x, x.y * x.y);
        float2 p1 = make_float2(x.z * x.z, x.w * x.w);
        a2h2[i * 2]     = __float22bfloat162_rn(p0);
        a2h2[i * 2 + 1] = __float22bfloat162_rn(p1);
    }
}

__global__ void finalize_kl(float* __restrict__ out) {
    double mean_log = g_sums[0] / (double)NW;
    double mean_sp  = g_sums[1] / (double)NW;
    double kl = -0.5 * ((double)SZ * mean_log - g_sums[2] - (double)SZ * mean_sp);
    out[(size_t)2 * SZ * SZ] = (float)kl;
}

// ---------------- main dual GEMM: mu=tf32 k8, Sigma=bf16 k16 -----------------
// CTA: 128x64, 256 threads, 8 warps (4m x 2n), warp tile 32x32, 2 CTA/SM.
// Swizzled smem (SW128 for tf32 tiles, SW64 for bf16 tiles), 3-stage cp.async.
#define BM 128
#define BN 64
#define BK 32
#define NCHUNK (SZ / BK)       // 128

#define OFF_A   0u
#define OFF_W1  16384u
#define OFF_A2  24576u
#define OFF_W2  32768u
#define STAGE_BYTES 36864u
#define SMEM_TOTAL (3 * STAGE_BYTES)    // 110592, 2 CTAs/SM

__global__ __launch_bounds__(256, 2)
void gemm_dual(const float* __restrict__ b_mu,
               const float* __restrict__ b_sigma,
               float* __restrict__ out) {
    extern __shared__ char smem[];
    const uint32_t sb = smem_u32(smem);

    const int tid = threadIdx.x;
    const int wid = tid >> 5;
    const int lid = tid & 31;
    const int lr  = lid >> 2;     // 0..7
    const int lc  = lid & 3;      // 0..3
    const int wm  = wid >> 1;     // 0..3
    const int wn  = wid & 1;      // 0..1
    const int m0 = blockIdx.y * BM;
    const int n0 = blockIdx.x * BN;

    const int lrow = lid & 7;
    const int lmat = lid >> 3;

    // Per-fragment swizzled addressing: addr = rowbase + ((cb + kbytes) ^ xr)
    // A tf32 (128B rows): row = wm*32+mt*16+(lmat&1)*8+lrow, cb=(lmat>>1)*16
    uint32_t rbA[2], xrA[2];
#pragma unroll
    for (int mt = 0; mt < 2; mt++) {
        uint32_t r = (uint32_t)(wm * 32 + mt * 16 + (lmat & 1) * 8 + lrow);
        rbA[mt] = r * 128u;
        xrA[mt] = (r * 16u) & 0x70u;
    }
    const uint32_t cbA = (uint32_t)((lmat >> 1) * 16);
    // W1 tf32: row = wn*32+ntp*16+(lmat>>1)*8+lrow, cb=(lmat&1)*16
    uint32_t rbW[2], xrW[2];
#pragma unroll
    for (int ntp = 0; ntp < 2; ntp++) {
        uint32_t r = (uint32_t)(wn * 32 + ntp * 16 + (lmat >> 1) * 8 + lrow);
        rbW[ntp] = r * 128u;
        xrW[ntp] = (r * 16u) & 0x70u;
    }
    const uint32_t cbW = (uint32_t)((lmat & 1) * 16);
    // A2 bf16 (64B rows): row = wm*32+mt*16+(lmat&1)*8+lrow, cb=(lmat>>1)*16
    uint32_t rbA2[2], xrA2[2];
#pragma unroll
    for (int mt = 0; mt < 2; mt++) {
        uint32_t r = (uint32_t)(wm * 32 + mt * 16 + (lmat & 1) * 8 + lrow);
        rbA2[mt] = r * 64u;
        xrA2[mt] = (r * 8u) & 0x30u;
    }
    const uint32_t cbA2 = (uint32_t)((lmat >> 1) * 16);
    // W2 bf16: row = wn*32+ntp*16+(lmat>>1)*8+lrow, cb=(lmat&1)*16
    uint32_t rbW2[2], xrW2[2];
#pragma unroll
    for (int ntp = 0; ntp < 2; ntp++) {
        uint32_t r = (uint32_t)(wn * 32 + ntp * 16 + (lmat >> 1) * 8 + lrow);
        rbW2[ntp] = r * 64u;
        xrW2[ntp] = (r * 8u) & 0x30u;
    }
    const uint32_t cbW2 = (uint32_t)((lmat & 1) * 16);

    float acc1[2][4][4];
    float acc2[2][4][4];
#pragma unroll
    for (int mt = 0; mt < 2; mt++)
#pragma unroll
        for (int nt = 0; nt < 4; nt++)
#pragma unroll
            for (int q = 0; q < 4; q++) { acc1[mt][nt][q] = 0.f; acc2[mt][nt][q] = 0.f; }

    // Stage loader: 9 x 16B cp.async per thread
    auto load_stage = [&](int chunk, int s) {
        const int k0 = chunk * BK;
        const uint32_t base = sb + (uint32_t)s * STAGE_BYTES;
#pragma unroll
        for (int i = 0; i < 4; i++) {           // A tf32: 128 rows x 8 c16
            int f = tid + i * 256;
            int r = f >> 3, cc = f & 7;
            cp16(base + OFF_A + swz128((uint32_t)(r * 128 + cc * 16)),
                 g_a + (size_t)(m0 + r) * SZ + k0 + cc * 4);
        }
#pragma unroll
        for (int i = 0; i < 2; i++) {           // W1 tf32: 64 rows x 8 c16
            int f = tid + i * 256;
            int r = f >> 3, cc = f & 7;
            cp16(base + OFF_W1 + swz128((uint32_t)(r * 128 + cc * 16)),
                 g_w1t + (size_t)(n0 + r) * SZ + k0 + cc * 4);
        }
#pragma unroll
        for (int i = 0; i < 2; i++) {           // A2h bf16: 128 rows x 4 u16
            int f = tid + i * 256;
            int r = f >> 2, u = f & 3;
            cp16(base + OFF_A2 + swz64((uint32_t)(r * 64 + u * 16)),
                 (const char*)g_a2h + ((size_t)(m0 + r) * SZ + k0) * 2 + u * 16);
        }
        {                                        // W2h bf16: 64 rows x 4 u16
            int r = tid >> 2, u = tid & 3;
            cp16(base + OFF_W2 + swz64((uint32_t)(r * 64 + u * 16)),
                 (const char*)g_w2h + ((size_t)(n0 + r) * SZ + k0) * 2 + u * 16);
        }
        asm volatile("cp.async.commit_group;" ::: "memory");
    };

    load_stage(0, 0);
    load_stage(1, 1);

    for (int c = 0; c < NCHUNK; c++) {
        const int s = c % 3;
        asm volatile("cp.async.wait_group 1;" ::: "memory");
        __syncthreads();
        if (c + 2 < NCHUNK) load_stage(c + 2, (c + 2) % 3);
        else asm volatile("cp.async.commit_group;" ::: "memory");

        const uint32_t stA  = sb + (uint32_t)s * STAGE_BYTES + OFF_A;
        const uint32_t stW1 = sb + (uint32_t)s * STAGE_BYTES + OFF_W1;
        const uint32_t stA2 = sb + (uint32_t)s * STAGE_BYTES + OFF_A2;
        const uint32_t stW2 = sb + (uint32_t)s * STAGE_BYTES + OFF_W2;

#pragma unroll
        for (int j = 0; j < 2; j++) {
            // ---- mu path: tf32 k8, ksteps 2j, 2j+1 ----
#pragma unroll
            for (int ksub = 0; ksub < 2; ksub++) {
                const uint32_t kb = (uint32_t)((j * 2 + ksub) * 32);
                uint32_t af[2][4];
#pragma unroll
                for (int mt = 0; mt < 2; mt++)
                    LDSM4(af[mt][0], af[mt][1], af[mt][2], af[mt][3],
                          stA + rbA[mt] + ((cbA + kb) ^ xrA[mt]));
#pragma unroll
                for (int ntp = 0; ntp < 2; ntp++) {
                    uint32_t wf[4];
                    LDSM4(wf[0], wf[1], wf[2], wf[3],
                          stW1 + rbW[ntp] + ((cbW + kb) ^ xrW[ntp]));
#pragma unroll
                    for (int h = 0; h < 2; h++) {
                        const int nt = ntp * 2 + h;
#pragma unroll
                        for (int mt = 0; mt < 2; mt++)
                            MMA_TF32U(acc1[mt][nt], af[mt][0], af[mt][1],
                                      af[mt][2], af[mt][3],
                                      wf[h * 2], wf[h * 2 + 1]);
                    }
                }
            }
            // ---- Sigma path: bf16 k16, kstep j ----
            {
                const uint32_t kb = (uint32_t)(j * 32);
                uint32_t a2f[2][4];
#pragma unroll
                for (int mt = 0; mt < 2; mt++)
                    LDSM4(a2f[mt][0], a2f[mt][1], a2f[mt][2], a2f[mt][3],
                          stA2 + rbA2[mt] + ((cbA2 + kb) ^ xrA2[mt]));
#pragma unroll
                for (int ntp = 0; ntp < 2; ntp++) {
                    uint32_t wf[4];
                    LDSM4(wf[0], wf[1], wf[2], wf[3],
                          stW2 + rbW2[ntp] + ((cbW2 + kb) ^ xrW2[ntp]));
#pragma unroll
                    for (int nb = 0; nb < 2; nb++) {
                        const int nt = ntp * 2 + nb;
#pragma unroll
                        for (int mt = 0; mt < 2; mt++)
                            MMA_BF16(acc2[mt][nt], a2f[mt][0], a2f[mt][1],
                                     a2f[mt][2], a2f[mt][3],
                                     wf[nb * 2], wf[nb * 2 + 1]);
                    }
                }
            }
        }
    }

    // ---------------- epilogue ----------------
    float* o1 = out;
    float* o2 = out + (size_t)SZ * SZ;
#pragma unroll
    for (int nt = 0; nt < 4; nt++) {
        int col = n0 + wn * 32 + nt * 8 + lc * 2;
        float bm0 = b_mu[col],  bm1 = b_mu[col + 1];
        float bs0 = softplusf(b_sigma[col]), bs1 = softplusf(b_sigma[col + 1]);
#pragma unroll
        for (int mt = 0; mt < 2; mt++) {
            int row = m0 + wm * 32 + mt * 16 + lr;
            float2 v;
            v.x = acc1[mt][nt][0] + bm0; v.y = acc1[mt][nt][1] + bm1;
            *(float2*)(o1 + (size_t)row * SZ + col) = v;
            v.x = acc1[mt][nt][2] + bm0; v.y = acc1[mt][nt][3] + bm1;
            *(float2*)(o1 + (size_t)(row + 8) * SZ + col) = v;
            v.x = acc2[mt][nt][0] + bs0; v.y = acc2[mt][nt][1] + bs1;
            *(float2*)(o2 + (size_t)row * SZ + col) = v;
            v.x = acc2[mt][nt][2] + bs0; v.y = acc2[mt][nt][3] + bs1;
            *(float2*)(o2 + (size_t)(row + 8) * SZ + col) = v;
        }
    }
}

// ---------------- launch -----------------------------------------------------
extern "C" void kernel_launch(void* const* d_in, const int* in_sizes, int n_in,
                              void* d_out, int out_size) {
    const float* mu_in   = (const float*)d_in[0];
    // d_in[1] = sigma_in : unused by the reference outputs
    const float* w_mu    = (const float*)d_in[2];
    const float* w_sigma = (const float*)d_in[3];
    const float* b_mu    = (const float*)d_in[4];
    const float* b_sigma = (const float*)d_in[5];
    float* out = (float*)d_out;

    cudaFuncSetAttribute(gemm_dual, cudaFuncAttributeMaxDynamicSharedMemorySize,
                         SMEM_TOTAL);

    init_kernel<<<1, 32>>>();
    prep_w<<<dim3(128, 128), dim3(32, 8)>>>(w_mu, w_sigma);
    prep_a<<<4096, 256>>>(mu_in);
    gemm_dual<<<dim3(SZ / BN, SZ / BM), 256, SMEM_TOTAL>>>(b_mu, b_sigma, out);
    finalize_kl<<<1, 1>>>(out);
}

// round 10
// speedup vs baseline: 2.0631x; 1.0990x over previous
#include <cuda_runtime.h>
#include <cuda_bf16.h>
#include <math.h>
#include <stdint.h>

#define SZ 4096
#define NW (SZ*SZ)

// ---------------- scratch (static __device__, no runtime alloc) -------------
__device__ __align__(16) float         g_a[NW];    // tf32-rounded mu_in [B][K]
__device__ __align__(16) float         g_w1t[NW];  // tf32-rounded w_mu^T [N][K]
__device__ __align__(16) __nv_bfloat16 g_a2h[NW];  // bf16(mu^2)        [B][K]
__device__ __align__(16) __nv_bfloat16 g_w2h[NW];  // bf16(sp(w_sig))^T [N][K]
__device__ double g_sums[3];   // [0]=sum log(sp) [1]=sum sp [2]=sum |w_mu|

__device__ __forceinline__ float softplusf(float x) {
    return x > 20.0f ? x : log1pf(expf(x));
}
__device__ __forceinline__ float tf32_rn(float x) {
    float y; asm("cvt.rna.tf32.f32 %0, %1;" : "=f"(y) : "f"(x)); return y;
}
__device__ __forceinline__ void cp16(uint32_t dst, const void* src) {
    asm volatile("cp.async.cg.shared.global [%0], [%1], 16;"
                 :: "r"(dst), "l"(__cvta_generic_to_global(src)));
}
__device__ __forceinline__ uint32_t smem_u32(const void* p) {
    uint32_t a;
    asm("{ .reg .u64 t; cvta.to.shared.u64 t, %1; cvt.u32.u64 %0, t; }"
        : "=r"(a) : "l"(p));
    return a;
}
__device__ __forceinline__ uint32_t swz128(uint32_t off) {
    return off ^ ((off >> 3) & 0x70);
}
__device__ __forceinline__ uint32_t swz64(uint32_t off) {
    return off ^ ((off >> 3) & 0x30);
}

#define LDSM4(r0, r1, r2, r3, addr) \
    asm volatile("ldmatrix.sync.aligned.m8n8.x4.shared.b16 {%0,%1,%2,%3}, [%4];" \
        : "=r"(r0), "=r"(r1), "=r"(r2), "=r"(r3) : "r"(addr))

#define MMA_TF32U(d, a0, a1, a2, a3, b0, b1) \
    asm volatile( \
        "mma.sync.aligned.m16n8k8.row.col.f32.tf32.tf32.f32 " \
        "{%0,%1,%2,%3}, {%4,%5,%6,%7}, {%8,%9}, {%0,%1,%2,%3};" \
        : "+f"((d)[0]), "+f"((d)[1]), "+f"((d)[2]), "+f"((d)[3]) \
        : "r"(a0), "r"(a1), "r"(a2), "r"(a3), "r"(b0), "r"(b1))

#define MMA_BF16(d, a0, a1, a2, a3, b0, b1) \
    asm volatile( \
        "mma.sync.aligned.m16n8k16.row.col.f32.bf16.bf16.f32 " \
        "{%0,%1,%2,%3}, {%4,%5,%6,%7}, {%8,%9}, {%0,%1,%2,%3};" \
        : "+f"((d)[0]), "+f"((d)[1]), "+f"((d)[2]), "+f"((d)[3]) \
        : "r"(a0), "r"(a1), "r"(a2), "r"(a3), "r"(b0), "r"(b1))

// ---------------- prep kernels ----------------------------------------------
__global__ void init_kernel() {
    if (threadIdx.x < 3) g_sums[threadIdx.x] = 0.0;
}

__global__ void prep_w(const float* __restrict__ w_mu,
                       const float* __restrict__ w_sigma) {
    __shared__ float t1[32][33];
    __shared__ float t2[32][33];
    __shared__ float red[3][256];
    const int bx = blockIdx.x * 32;   // n
    const int by = blockIdx.y * 32;   // k
    const int tx = threadIdx.x, ty = threadIdx.y;
    const int tid = ty * 32 + tx;

    float s_log = 0.f, s_sp = 0.f, s_abs = 0.f;
#pragma unroll
    for (int i = 0; i < 4; i++) {
        int k = by + ty + i * 8;
        int n = bx + tx;
        float wm = w_mu[(size_t)k * SZ + n];
        float ws = w_sigma[(size_t)k * SZ + n];
        float sp = softplusf(ws);
        s_log += logf(sp);
        s_sp  += sp;
        s_abs += fabsf(wm);
        t1[ty + i * 8][tx] = tf32_rn(wm);
        t2[ty + i * 8][tx] = sp;
    }
    __syncthreads();
#pragma unroll
    for (int i = 0; i < 4; i++) {
        int n = bx + ty + i * 8;
        int k = by + tx;
        g_w1t[(size_t)n * SZ + k] = t1[tx][ty + i * 8];
        g_w2h[(size_t)n * SZ + k] = __float2bfloat16_rn(t2[tx][ty + i * 8]);
    }

    red[0][tid] = s_log; red[1][tid] = s_sp; red[2][tid] = s_abs;
    __syncthreads();
    for (int off = 128; off > 0; off >>= 1) {
        if (tid < off) {
            red[0][tid] += red[0][tid + off];
            red[1][tid] += red[1][tid + off];
            red[2][tid] += red[2][tid + off];
        }
        __syncthreads();
    }
    if (tid == 0) {
        atomicAdd(&g_sums[0], (double)red[0][0]);
        atomicAdd(&g_sums[1], (double)red[1][0]);
        atomicAdd(&g_sums[2], (double)red[2][0]);
    }
}

__global__ void prep_a(const float* __restrict__ mu) {
    const float4* m4 = (const float4*)mu;
    float4* a4 = (float4*)g_a;
    __nv_bfloat162* a2h2 = (__nv_bfloat162*)g_a2h;
    int stride = gridDim.x * blockDim.x;
    for (int i = blockIdx.x * blockDim.x + threadIdx.x; i < NW / 4; i += stride) {
        float4 x = m4[i];
        float4 a;
        a.x = tf32_rn(x.x); a.y = tf32_rn(x.y);
        a.z = tf32_rn(x.z); a.w = tf32_rn(x.w);
        a4[i] = a;
        float2 p0 = make_float2(x.x * x.x, x.y * x.y);
        float2 p1 = make_float2(x.z * x.z, x.w * x.w);
        a2h2[i * 2]     = __float22bfloat162_rn(p0);
        a2h2[i * 2 + 1] = __float22bfloat162_rn(p1);
    }
}

__global__ void finalize_kl(float* __restrict__ out) {
    double mean_log = g_sums[0] / (double)NW;
    double mean_sp  = g_sums[1] / (double)NW;
    double kl = -0.5 * ((double)SZ * mean_log - g_sums[2] - (double)SZ * mean_sp);
    out[(size_t)2 * SZ * SZ] = (float)kl;
}

// ---------------- main dual GEMM: mu=tf32 k8, Sigma=bf16 k16 -----------------
// CTA: 128x64, 128 threads, 4 warps (2m x 2n), warp tile 64x32, 2 CTA/SM.
// Swizzled smem (SW128 tf32 / SW64 bf16), 3-stage cp.async.
#define BM 128
#define BN 64
#define BK 32
#define NCHUNK (SZ / BK)       // 128

#define OFF_A   0u
#define OFF_W1  16384u
#define OFF_A2  24576u
#define OFF_W2  32768u
#define STAGE_BYTES 36864u
#define SMEM_TOTAL (3 * STAGE_BYTES)    // 110592, 2 CTAs/SM

__global__ __launch_bounds__(128, 2)
void gemm_dual(const float* __restrict__ b_mu,
               const float* __restrict__ b_sigma,
               float* __restrict__ out) {
    extern __shared__ char smem[];
    const uint32_t sb = smem_u32(smem);

    const int tid = threadIdx.x;
    const int wid = tid >> 5;
    const int lid = tid & 31;
    const int lr  = lid >> 2;     // 0..7
    const int lc  = lid & 3;      // 0..3
    const int wm  = wid & 1;      // 0..1 (64 rows)
    const int wn  = wid >> 1;     // 0..1 (32 cols)
    const int m0 = blockIdx.y * BM;
    const int n0 = blockIdx.x * BN;

    const int lrow = lid & 7;
    const int lmat = lid >> 3;

    // Swizzled fragment addressing: addr = rowbase + ((cb + kbytes) ^ xr)
    uint32_t rbA[4], xrA[4];
#pragma unroll
    for (int mt = 0; mt < 4; mt++) {
        uint32_t r = (uint32_t)(wm * 64 + mt * 16 + (lmat & 1) * 8 + lrow);
        rbA[mt] = r * 128u;
        xrA[mt] = (r * 16u) & 0x70u;
    }
    const uint32_t cbA = (uint32_t)((lmat >> 1) * 16);
    uint32_t rbW[2], xrW[2];
#pragma unroll
    for (int ntp = 0; ntp < 2; ntp++) {
        uint32_t r = (uint32_t)(wn * 32 + ntp * 16 + (lmat >> 1) * 8 + lrow);
        rbW[ntp] = r * 128u;
        xrW[ntp] = (r * 16u) & 0x70u;
    }
    const uint32_t cbW = (uint32_t)((lmat & 1) * 16);
    uint32_t rbA2[4], xrA2[4];
#pragma unroll
    for (int mt = 0; mt < 4; mt++) {
        uint32_t r = (uint32_t)(wm * 64 + mt * 16 + (lmat & 1) * 8 + lrow);
        rbA2[mt] = r * 64u;
        xrA2[mt] = (r * 8u) & 0x30u;
    }
    const uint32_t cbA2 = (uint32_t)((lmat >> 1) * 16);
    uint32_t rbW2[2], xrW2[2];
#pragma unroll
    for (int ntp = 0; ntp < 2; ntp++) {
        uint32_t r = (uint32_t)(wn * 32 + ntp * 16 + (lmat >> 1) * 8 + lrow);
        rbW2[ntp] = r * 64u;
        xrW2[ntp] = (r * 8u) & 0x30u;
    }
    const uint32_t cbW2 = (uint32_t)((lmat & 1) * 16);

    float acc1[4][4][4];
    float acc2[4][4][4];
#pragma unroll
    for (int mt = 0; mt < 4; mt++)
#pragma unroll
        for (int nt = 0; nt < 4; nt++)
#pragma unroll
            for (int q = 0; q < 4; q++) { acc1[mt][nt][q] = 0.f; acc2[mt][nt][q] = 0.f; }

    // Stage loader: 18 x 16B cp.async per thread (128 threads)
    auto load_stage = [&](int chunk, int s) {
        const int k0 = chunk * BK;
        const uint32_t base = sb + (uint32_t)s * STAGE_BYTES;
#pragma unroll
        for (int i = 0; i < 8; i++) {           // A tf32: 128 rows x 8 c16
            int f = tid + i * 128;
            int r = f >> 3, cc = f & 7;
            cp16(base + OFF_A + swz128((uint32_t)(r * 128 + cc * 16)),
                 g_a + (size_t)(m0 + r) * SZ + k0 + cc * 4);
        }
#pragma unroll
        for (int i = 0; i < 4; i++) {           // W1 tf32: 64 rows x 8 c16
            int f = tid + i * 128;
            int r = f >> 3, cc = f & 7;
            cp16(base + OFF_W1 + swz128((uint32_t)(r * 128 + cc * 16)),
                 g_w1t + (size_t)(n0 + r) * SZ + k0 + cc * 4);
        }
#pragma unroll
        for (int i = 0; i < 4; i++) {           // A2h bf16: 128 rows x 4 u16
            int f = tid + i * 128;
            int r = f >> 2, u = f & 3;
            cp16(base + OFF_A2 + swz64((uint32_t)(r * 64 + u * 16)),
                 (const char*)g_a2h + ((size_t)(m0 + r) * SZ + k0) * 2 + u * 16);
        }
#pragma unroll
        for (int i = 0; i < 2; i++) {           // W2h bf16: 64 rows x 4 u16
            int f = tid + i * 128;
            int r = f >> 2, u = f & 3;
            cp16(base + OFF_W2 + swz64((uint32_t)(r * 64 + u * 16)),
                 (const char*)g_w2h + ((size_t)(n0 + r) * SZ + k0) * 2 + u * 16);
        }
        asm volatile("cp.async.commit_group;" ::: "memory");
    };

    load_stage(0, 0);
    load_stage(1, 1);

    for (int c = 0; c < NCHUNK; c++) {
        const int s = c % 3;
        asm volatile("cp.async.wait_group 1;" ::: "memory");
        __syncthreads();
        if (c + 2 < NCHUNK) load_stage(c + 2, (c + 2) % 3);
        else asm volatile("cp.async.commit_group;" ::: "memory");

        const uint32_t stA  = sb + (uint32_t)s * STAGE_BYTES + OFF_A;
        const uint32_t stW1 = sb + (uint32_t)s * STAGE_BYTES + OFF_W1;
        const uint32_t stA2 = sb + (uint32_t)s * STAGE_BYTES + OFF_A2;
        const uint32_t stW2 = sb + (uint32_t)s * STAGE_BYTES + OFF_W2;

#pragma unroll
        for (int j = 0; j < 2; j++) {
            // ---- mu path: tf32 k8, ksteps 2j, 2j+1 ----
#pragma unroll
            for (int ksub = 0; ksub < 2; ksub++) {
                const uint32_t kb = (uint32_t)((j * 2 + ksub) * 32);
                uint32_t af[4][4];
#pragma unroll
                for (int mt = 0; mt < 4; mt++)
                    LDSM4(af[mt][0], af[mt][1], af[mt][2], af[mt][3],
                          stA + rbA[mt] + ((cbA + kb) ^ xrA[mt]));
#pragma unroll
                for (int ntp = 0; ntp < 2; ntp++) {
                    uint32_t wf[4];
                    LDSM4(wf[0], wf[1], wf[2], wf[3],
                          stW1 + rbW[ntp] + ((cbW + kb) ^ xrW[ntp]));
#pragma unroll
                    for (int h = 0; h < 2; h++) {
                        const int nt = ntp * 2 + h;
#pragma unroll
                        for (int mt = 0; mt < 4; mt++)
                            MMA_TF32U(acc1[mt][nt], af[mt][0], af[mt][1],
                                      af[mt][2], af[mt][3],
                                      wf[h * 2], wf[h * 2 + 1]);
                    }
                }
            }
            // ---- Sigma path: bf16 k16, kstep j ----
            {
                const uint32_t kb = (uint32_t)(j * 32);
                uint32_t a2f[4][4];
#pragma unroll
                for (int mt = 0; mt < 4; mt++)
                    LDSM4(a2f[mt][0], a2f[mt][1], a2f[mt][2], a2f[mt][3],
                          stA2 + rbA2[mt] + ((cbA2 + kb) ^ xrA2[mt]));
#pragma unroll
                for (int ntp = 0; ntp < 2; ntp++) {
                    uint32_t wf[4];
                    LDSM4(wf[0], wf[1], wf[2], wf[3],
                          stW2 + rbW2[ntp] + ((cbW2 + kb) ^ xrW2[ntp]));
#pragma unroll
                    for (int nb = 0; nb < 2; nb++) {
                        const int nt = ntp * 2 + nb;
#pragma unroll
                        for (int mt = 0; mt < 4; mt++)
                            MMA_BF16(acc2[mt][nt], a2f[mt][0], a2f[mt][1],
                                     a2f[mt][2], a2f[mt][3],
                                     wf[nb * 2], wf[nb * 2 + 1]);
                    }
                }
            }
        }
    }

    // ---------------- epilogue ----------------
    float* o1 = out;
    float* o2 = out + (size_t)SZ * SZ;
#pragma unroll
    for (int nt = 0; nt < 4; nt++) {
        int col = n0 + wn * 32 + nt * 8 + lc * 2;
        float bm0 = b_mu[col],  bm1 = b_mu[col + 1];
        float bs0 = softplusf(b_sigma[col]), bs1 = softplusf(b_sigma[col + 1]);
#pragma unroll
        for (int mt = 0; mt < 4; mt++) {
            int row = m0 + wm * 64 + mt * 16 + lr;
            float2 v;
            v.x = acc1[mt][nt][0] + bm0; v.y = acc1[mt][nt][1] + bm1;
            *(float2*)(o1 + (size_t)row * SZ + col) = v;
            v.x = acc1[mt][nt][2] + bm0; v.y = acc1[mt][nt][3] + bm1;
            *(float2*)(o1 + (size_t)(row + 8) * SZ + col) = v;
            v.x = acc2[mt][nt][0] + bs0; v.y = acc2[mt][nt][1] + bs1;
            *(float2*)(o2 + (size_t)row * SZ + col) = v;
            v.x = acc2[mt][nt][2] + bs0; v.y = acc2[mt][nt][3] + bs1;
            *(float2*)(o2 + (size_t)(row + 8) * SZ + col) = v;
        }
    }
}

// ---------------- launch -----------------------------------------------------
extern "C" void kernel_launch(void* const* d_in, const int* in_sizes, int n_in,
                              void* d_out, int out_size) {
    const float* mu_in   = (const float*)d_in[0];
    // d_in[1] = sigma_in : unused by the reference outputs
    const float* w_mu    = (const float*)d_in[2];
    const float* w_sigma = (const float*)d_in[3];
    const float* b_mu    = (const float*)d_in[4];
    const float* b_sigma = (const float*)d_in[5];
    float* out = (float*)d_out;

    cudaFuncSetAttribute(gemm_dual, cudaFuncAttributeMaxDynamicSharedMemorySize,
                         SMEM_TOTAL);

    init_kernel<<<1, 32>>>();
    prep_w<<<dim3(128, 128), dim3(32, 8)>>>(w_mu, w_sigma);
    prep_a<<<4096, 256>>>(mu_in);
    gemm_dual<<<dim3(SZ / BN, SZ / BM), 128, SMEM_TOTAL>>>(b_mu, b_sigma, out);
    finalize_kl<<<1, 1>>>(out);
}